// round 4
// baseline (speedup 1.0000x reference)
#include <cuda_runtime.h>
#include <cuda_bf16.h>
#include <math.h>
#include <stdint.h>

#define N_PRED 65536
#define N_GT   128
#define N_CLS  256
#define MAX_DYN 10
#define GEPS   1e-6f
#define IOU_THRES 0.25f
#define CAND_C 512      // per-row LSA candidate cap (need >=128)
#define GC_NEED 1408    // per-gt dynamic candidate depth (10 + 128 + 10*127)
#define GC_CAP  2048    // collection cap before sort

// ------------------- scratch (device globals; no runtime allocation) -------------------
__device__ float  d_cost[N_GT][N_PRED];   // 32MB  cost_T[g][p]
__device__ float  d_giou[N_GT][N_PRED];   // 32MB  giou_T[g][p]
__device__ float  d_maxg[N_GT];
__device__ int    d_order[N_GT];
__device__ int    d_labels[N_GT];

__device__ int    d_ccand_idx[N_GT][CAND_C];
__device__ float  d_ccand_val[N_GT][CAND_C];
__device__ int    d_ccand_cnt[N_GT];

__device__ int    d_gcand_idx[N_GT][GC_NEED];
__device__ int    d_gcand_cnt[N_GT];

__device__ double d_v[N_PRED];
__device__ double d_shortest[N_PRED];
__device__ int    d_path[N_PRED];
__device__ int    d_stampA[N_PRED];
__device__ int    d_stampSC[N_PRED];
__device__ int    d_row4col[N_PRED];
__device__ int    d_col4row[N_GT];
__device__ int    d_T[N_GT * CAND_C];

// monotonic ascending key for float
__device__ __forceinline__ unsigned fkey(float f) {
    unsigned u = __float_as_uint(f);
    return (u & 0x80000000u) ? ~u : (u | 0x80000000u);
}

// ------------------- label decode (int32 vs int64 input sniff) -------------------
__global__ void k_labels(const void* lab) {
    __shared__ int is32;
    if (threadIdx.x == 0) {
        const unsigned long long* p = (const unsigned long long*)lab;
        int f = 0;
        for (int i = 0; i < 64; i++) { if (p[i] >> 32) { f = 1; break; } }
        is32 = f;
    }
    __syncthreads();
    int t = threadIdx.x;
    if (t < N_GT) {
        long long v;
        if (is32) v = (long long)((const int*)lab)[t];
        else      v = ((const long long*)lab)[t];
        int iv = (int)v;
        if (iv < 0) iv = 0;
        if (iv >= N_CLS) iv = N_CLS - 1;
        d_labels[t] = iv;
    }
}

// ------------------- cost + giou matrices (precise, unfused fp32) -------------------
__global__ void k_cost(const float* __restrict__ pc, const float* __restrict__ ps,
                       const float* __restrict__ cls,
                       const float* __restrict__ gc, const float* __restrict__ gs) {
    __shared__ float glo0[N_GT], glo1[N_GT], glo2[N_GT];
    __shared__ float ghi0[N_GT], ghi1[N_GT], ghi2[N_GT];
    __shared__ float gvol[N_GT];
    __shared__ int   glab[N_GT];
    int t = threadIdx.x;  // blockDim = 128
    {
        float c0 = gc[t*3+0], c1 = gc[t*3+1], c2 = gc[t*3+2];
        float s0 = gs[t*3+0], s1 = gs[t*3+1], s2 = gs[t*3+2];
        float h0s = __fmul_rn(s0, 0.5f), h1s = __fmul_rn(s1, 0.5f), h2s = __fmul_rn(s2, 0.5f);
        float l0 = __fsub_rn(c0, h0s), l1 = __fsub_rn(c1, h1s), l2 = __fsub_rn(c2, h2s);
        float h0 = __fadd_rn(c0, h0s), h1 = __fadd_rn(c1, h1s), h2 = __fadd_rn(c2, h2s);
        glo0[t]=l0; glo1[t]=l1; glo2[t]=l2; ghi0[t]=h0; ghi1[t]=h1; ghi2[t]=h2;
        gvol[t] = __fmul_rn(__fmul_rn(__fsub_rn(h0,l0), __fsub_rn(h1,l1)), __fsub_rn(h2,l2));
        glab[t] = d_labels[t];
    }
    __syncthreads();
    int p = blockIdx.x * blockDim.x + t;
    float c0 = pc[p*3+0], c1 = pc[p*3+1], c2 = pc[p*3+2];
    float s0 = ps[p*3+0], s1 = ps[p*3+1], s2 = ps[p*3+2];
    float h0s = __fmul_rn(s0, 0.5f), h1s = __fmul_rn(s1, 0.5f), h2s = __fmul_rn(s2, 0.5f);
    float pl0 = __fsub_rn(c0, h0s), pl1 = __fsub_rn(c1, h1s), pl2 = __fsub_rn(c2, h2s);
    float ph0 = __fadd_rn(c0, h0s), ph1 = __fadd_rn(c1, h1s), ph2 = __fadd_rn(c2, h2s);
    float vol1 = __fmul_rn(__fmul_rn(__fsub_rn(ph0,pl0), __fsub_rn(ph1,pl1)), __fsub_rn(ph2,pl2));
    const float* clsrow = cls + (size_t)p * N_CLS;

    #pragma unroll 4
    for (int g = 0; g < N_GT; g++) {
        float d0 = fmaxf(__fsub_rn(fminf(ph0, ghi0[g]), fmaxf(pl0, glo0[g])), 0.f);
        float d1 = fmaxf(__fsub_rn(fminf(ph1, ghi1[g]), fmaxf(pl1, glo1[g])), 0.f);
        float d2 = fmaxf(__fsub_rn(fminf(ph2, ghi2[g]), fmaxf(pl2, glo2[g])), 0.f);
        float ov = __fmul_rn(__fmul_rn(d0, d1), d2);
        float un = fmaxf(__fsub_rn(__fadd_rn(vol1, gvol[g]), ov), GEPS);
        float iou = __fdiv_rn(ov, un);
        float e0 = fmaxf(__fsub_rn(fmaxf(ph0, ghi0[g]), fminf(pl0, glo0[g])), 0.f);
        float e1 = fmaxf(__fsub_rn(fmaxf(ph1, ghi1[g]), fminf(pl1, glo1[g])), 0.f);
        float e2 = fmaxf(__fsub_rn(fmaxf(ph2, ghi2[g]), fminf(pl2, glo2[g])), 0.f);
        float enc = fmaxf(__fmul_rn(__fmul_rn(e0, e1), e2), GEPS);
        float gi = __fsub_rn(iou, __fdiv_rn(__fsub_rn(enc, un), enc));
        float cv = __ldg(clsrow + glab[g]);
        float sig = __fdiv_rn(1.0f, __fadd_rn(1.0f, expf(-cv)));
        d_giou[g][p] = gi;
        d_cost[g][p] = __fadd_rn(-sig, __fmul_rn(-2.0f, gi));
    }
}

// ------------------- per-gt max giou -------------------
__global__ void k_maxg() {
    int g = blockIdx.x, t = threadIdx.x;
    float m = -1e30f;
    for (int j = t; j < N_PRED; j += blockDim.x) m = fmaxf(m, d_giou[g][j]);
    __shared__ float red[256];
    red[t] = m; __syncthreads();
    for (int off = blockDim.x >> 1; off > 0; off >>= 1) {
        if (t < off) red[t] = fmaxf(red[t], red[t + off]);
        __syncthreads();
    }
    if (t == 0) d_maxg[g] = red[0];
}

// ------------------- stable argsort (ascending) of maxg -------------------
__global__ void k_order() {
    __shared__ float v[N_GT];
    int t = threadIdx.x;
    v[t] = d_maxg[t];
    __syncthreads();
    float mv = v[t]; int r = 0;
    for (int j = 0; j < N_GT; j++) {
        float o = v[j];
        if (o < mv || (o == mv && j < t)) r++;
    }
    d_order[r] = t;
}

// ------------------- per-row 128-smallest cost candidates (radix select, superset) --------
__global__ void k_topk_cost() {
    int row = blockIdx.x, tid = threadIdx.x, nth = blockDim.x;
    __shared__ unsigned hist[256];
    __shared__ unsigned s_pfx;
    __shared__ int s_need;
    __shared__ int s_cnt;
    if (tid == 0) { s_pfx = 0; s_need = 128; }
    for (int l = 0; l < 3; l++) {
        for (int b = tid; b < 256; b += nth) hist[b] = 0;
        __syncthreads();
        unsigned pfx = s_pfx;
        for (int j = tid; j < N_PRED; j += nth) {
            unsigned k = fkey(d_cost[row][j]);
            bool ok = (l == 0) || ((k >> (32 - 8 * l)) == pfx);
            if (ok) atomicAdd(&hist[(k >> (24 - 8 * l)) & 255u], 1u);
        }
        __syncthreads();
        if (tid == 0) {
            int need = s_need; unsigned cum = 0; int b = 0;
            for (; b < 255; b++) { if (cum + hist[b] >= (unsigned)need) break; cum += hist[b]; }
            s_need = need - (int)cum;
            s_pfx = (s_pfx << 8) | (unsigned)b;
        }
        __syncthreads();
    }
    if (tid == 0) s_cnt = 0;
    __syncthreads();
    unsigned pfx24 = s_pfx;
    for (int j = tid; j < N_PRED; j += nth) {
        float v = d_cost[row][j];
        unsigned k = fkey(v);
        if ((k >> 8) <= pfx24) {
            int slot = atomicAdd(&s_cnt, 1);
            if (slot < CAND_C) { d_ccand_idx[row][slot] = j; d_ccand_val[row][slot] = v; }
        }
    }
    __syncthreads();
    if (tid == 0) d_ccand_cnt[row] = (s_cnt < CAND_C) ? s_cnt : CAND_C;
}

// ------------------- per-gt top-1408 giou (>thres), exact sort desc by (val, idx asc) ----
__global__ void k_topg() {
    int row = blockIdx.x, tid = threadIdx.x, nth = blockDim.x;
    __shared__ unsigned hist[256];
    __shared__ unsigned s_pfx;
    __shared__ int s_need, s_all, s_cnt;
    __shared__ unsigned long long buf[GC_CAP];
    if (tid == 0) { s_pfx = 0; s_need = GC_NEED; s_all = 0; }
    for (int l = 0; l < 3; l++) {
        for (int b = tid; b < 256; b += nth) hist[b] = 0;
        __syncthreads();
        unsigned pfx = s_pfx;
        for (int j = tid; j < N_PRED; j += nth) {
            float g = d_giou[row][j];
            if (!(g > IOU_THRES)) continue;
            unsigned k = ~fkey(g);  // ascending k == descending giou
            bool ok = (l == 0) || ((k >> (32 - 8 * l)) == pfx);
            if (ok) atomicAdd(&hist[(k >> (24 - 8 * l)) & 255u], 1u);
        }
        __syncthreads();
        if (tid == 0) {
            if (l == 0) {
                unsigned tot = 0;
                for (int b = 0; b < 256; b++) tot += hist[b];
                if (tot <= (unsigned)GC_NEED) s_all = 1;
            }
            if (!s_all) {
                int need = s_need; unsigned cum = 0; int b = 0;
                for (; b < 255; b++) { if (cum + hist[b] >= (unsigned)need) break; cum += hist[b]; }
                s_need = need - (int)cum;
                s_pfx = (s_pfx << 8) | (unsigned)b;
            }
        }
        __syncthreads();
    }
    for (int i = tid; i < GC_CAP; i += nth) buf[i] = 0xFFFFFFFFFFFFFFFFull;
    if (tid == 0) s_cnt = 0;
    __syncthreads();
    unsigned pfx24 = s_pfx; int all = s_all;
    for (int j = tid; j < N_PRED; j += nth) {
        float g = d_giou[row][j];
        if (!(g > IOU_THRES)) continue;
        unsigned k = ~fkey(g);
        if (all || ((k >> 8) <= pfx24)) {
            int slot = atomicAdd(&s_cnt, 1);
            if (slot < GC_CAP) buf[slot] = ((unsigned long long)k << 32) | (unsigned)j;
        }
    }
    __syncthreads();
    // bitonic sort GC_CAP ascending (=> giou desc, idx asc)
    for (int k = 2; k <= GC_CAP; k <<= 1) {
        for (int j = k >> 1; j > 0; j >>= 1) {
            for (int i = tid; i < GC_CAP; i += nth) {
                int ixj = i ^ j;
                if (ixj > i) {
                    bool up = ((i & k) == 0);
                    unsigned long long a = buf[i], b = buf[ixj];
                    if ((a > b) == up) { buf[i] = b; buf[ixj] = a; }
                }
            }
            __syncthreads();
        }
    }
    int cnt = s_cnt; if (cnt > GC_CAP) cnt = GC_CAP; if (cnt > GC_NEED) cnt = GC_NEED;
    for (int i = tid; i < cnt; i += nth)
        d_gcand_idx[row][i] = (int)(buf[i] & 0xFFFFFFFFull);
    if (tid == 0) d_gcand_cnt[row] = cnt;
}

// ------------------- init LSA scratch -------------------
__global__ void k_init() {
    int i = blockIdx.x * blockDim.x + threadIdx.x;
    if (i < N_PRED) {
        d_v[i] = 0.0; d_stampA[i] = 0; d_stampSC[i] = 0; d_row4col[i] = -1;
    }
}

// ------------------- sparse Jonker-Volgenant LSA (single block, fp64 duals) -------------
__global__ void k_lsa() {
    int tid = threadIdx.x, nth = blockDim.x;  // 256
    __shared__ double u[N_GT];
    __shared__ int SR[N_GT];
    __shared__ int s_nSR, s_row, s_sink, s_nT;
    __shared__ double s_minval;
    __shared__ double rv[256];
    __shared__ int ri[256];
    for (int i = tid; i < N_GT; i += nth) { u[i] = 0.0; d_col4row[i] = -1; }
    __syncthreads();

    for (int cur = 0; cur < N_GT; cur++) {
        int stamp = cur + 1;
        if (tid == 0) { s_nSR = 0; s_row = cur; s_sink = -1; s_nT = 0; s_minval = 0.0; }
        __syncthreads();
        for (int step = 0; step < N_GT; step++) {
            int i = s_row;
            if (tid == 0) { SR[s_nSR++] = i; }
            double mv0 = s_minval, ui = u[i];
            int cnt = d_ccand_cnt[i];
            for (int slot = tid; slot < cnt; slot += nth) {
                int j = d_ccand_idx[i][slot];
                if (d_stampSC[j] == stamp) continue;
                // match reference order: ((min_val + cost) - u) - v
                double r = ((mv0 + (double)d_ccand_val[i][slot]) - ui) - d_v[j];
                if (d_stampA[j] != stamp) {
                    d_stampA[j] = stamp;
                    d_shortest[j] = r; d_path[j] = i;
                    int t2 = atomicAdd(&s_nT, 1);
                    d_T[t2] = j;
                } else if (r < d_shortest[j]) {
                    d_shortest[j] = r; d_path[j] = i;
                }
            }
            __syncthreads();
            double bv = 1e300; int bj = 0x7fffffff;
            int nT = s_nT;
            for (int t2 = tid; t2 < nT; t2 += nth) {
                int j = d_T[t2];
                if (d_stampSC[j] == stamp) continue;
                double sv = d_shortest[j];
                if (sv < bv || (sv == bv && j < bj)) { bv = sv; bj = j; }
            }
            rv[tid] = bv; ri[tid] = bj;
            __syncthreads();
            for (int off = nth >> 1; off > 0; off >>= 1) {
                if (tid < off) {
                    double ov = rv[tid + off]; int oj = ri[tid + off];
                    if (ov < rv[tid] || (ov == rv[tid] && oj < ri[tid])) { rv[tid] = ov; ri[tid] = oj; }
                }
                __syncthreads();
            }
            if (tid == 0) {
                int j = ri[0];
                if (j >= 0 && j < N_PRED) {   // guard: never wild-write
                    s_minval = rv[0];
                    d_stampSC[j] = stamp;
                    if (d_row4col[j] < 0) s_sink = j; else s_row = d_row4col[j];
                } else {
                    s_sink = -2;  // abort this augmentation (should never happen)
                }
            }
            __syncthreads();
            if (s_sink != -1) break;
        }
        if (s_sink >= 0) {
            if (tid == 0) {
                u[cur] += s_minval;
                for (int k = 1; k < s_nSR; k++) {
                    int i2 = SR[k];
                    u[i2] += s_minval - d_shortest[d_col4row[i2]];
                }
            }
            int nT = s_nT; double mv = s_minval;
            for (int t2 = tid; t2 < nT; t2 += nth) {
                int j = d_T[t2];
                if (d_stampSC[j] == stamp) d_v[j] -= mv - d_shortest[j];
            }
            if (tid == 0) {
                int j = s_sink;
                for (int it = 0; it < N_GT + 1 && j >= 0; it++) {
                    int i2 = d_path[j];
                    d_row4col[j] = i2;
                    int tmp = d_col4row[i2];
                    d_col4row[i2] = j;
                    j = tmp;
                    if (i2 == cur) break;
                }
            }
        }
        __syncthreads();
    }
}

// ------------------- dynamic assignment + output write (FLOAT32 output) -------------------
__global__ void k_dyn(float* __restrict__ out) {
    __shared__ unsigned used[N_PRED / 32];  // 8KB bitmap
    __shared__ int res_p[1408];
    __shared__ int res_g[1408];
    int tid = threadIdx.x;
    for (int i = tid; i < N_PRED / 32; i += blockDim.x) used[i] = 0;
    __syncthreads();
    if (tid < N_GT) {
        int p = d_col4row[tid];
        if (p >= 0 && p < N_PRED) atomicOr(&used[p >> 5], 1u << (p & 31));
        res_p[tid] = p;     // pred_indices
        res_g[tid] = tid;   // gt_indices
    }
    __syncthreads();
    if (tid < 32) {
        int lane = tid;
        for (int t = 0; t < N_GT; t++) {
            int g = d_order[t];
            int cnt = d_gcand_cnt[g];
            int picked = 0;
            for (int base = 0; base < cnt && picked < MAX_DYN; base += 32) {
                int idx = -1;
                if (base + lane < cnt) idx = d_gcand_idx[g][base + lane];
                bool elig = (idx >= 0) && (idx < N_PRED) && !((used[idx >> 5] >> (idx & 31)) & 1u);
                unsigned m = __ballot_sync(0xffffffffu, elig);
                int K = MAX_DYN - picked;
                int pre = __popc(m & ((1u << lane) - 1u));
                if (elig && pre < K) {
                    atomicOr(&used[idx >> 5], 1u << (idx & 31));
                    res_p[128 + t * MAX_DYN + picked + pre] = idx;
                    res_g[128 + t * MAX_DYN + picked + pre] = g;
                }
                int got = __popc(m); if (got > K) got = K;
                picked += got;
                __syncwarp();
            }
            if (lane >= picked && lane < MAX_DYN) {
                res_p[128 + t * MAX_DYN + lane] = -1;
                res_g[128 + t * MAX_DYN + lane] = -1;
            }
            __syncwarp();
        }
    }
    __syncthreads();
    // Output layout: [combined_preds(1408), combined_gts(1408)] as float32 values
    for (int i = tid; i < 1408; i += blockDim.x) {
        out[i]        = (float)res_p[i];
        out[1408 + i] = (float)res_g[i];
    }
}

// ------------------- launch (inputs resolved by element count, order-agnostic) -----------
extern "C" void kernel_launch(void* const* d_in, const int* in_sizes, int n_in,
                              void* d_out, int out_size) {
    const float* all_centers = 0;
    const float* all_sizes   = 0;
    const float* all_cls     = 0;
    const float* gt_centers  = 0;
    const float* gt_sizes    = 0;
    const void*  gt_labels   = 0;
    int seen196 = 0, seen384 = 0;
    for (int i = 0; i < n_in; i++) {
        long long s = in_sizes[i];
        if (s == (long long)N_PRED * N_CLS) {
            all_cls = (const float*)d_in[i];
        } else if (s == (long long)N_PRED * 3) {
            if (seen196++ == 0) all_centers = (const float*)d_in[i];
            else                all_sizes   = (const float*)d_in[i];
        } else if (s == (long long)N_GT * 3) {
            if (seen384++ == 0) gt_centers = (const float*)d_in[i];
            else                gt_sizes   = (const float*)d_in[i];
        } else if (s == (long long)N_GT) {
            gt_labels = d_in[i];
        }
        // s == N_PRED (objness) unused: weight 0
    }

    k_labels<<<1, 128>>>(gt_labels);
    k_cost<<<N_PRED / 128, 128>>>(all_centers, all_sizes, all_cls, gt_centers, gt_sizes);
    k_maxg<<<N_GT, 256>>>();
    k_order<<<1, N_GT>>>();
    k_topk_cost<<<N_GT, 256>>>();
    k_init<<<N_PRED / 256, 256>>>();
    k_lsa<<<1, 256>>>();
    k_topg<<<N_GT, 256>>>();
    k_dyn<<<1, 256>>>((float*)d_out);
}

// round 5
// speedup vs baseline: 1.5397x; 1.5397x over previous
#include <cuda_runtime.h>
#include <math.h>
#include <stdint.h>

#define N_PRED 65536
#define N_GT   128
#define N_CLS  256
#define MAX_DYN 10
#define GEPS   1e-6f
#define IOU_THRES 0.25f
#define CAND_C 512      // per-row LSA candidate cap (need >=128)
#define GC_NEED 1408    // per-gt dynamic candidate depth (10 + 128 + 10*127)
#define GC_CAP  2048    // collection cap before sort
#define NBMW   (N_PRED/32)   // 2048 bitmap words
#define LSA_CAP 18176        // smem LSA capacity (compact columns)
#define LSA_DYN_BYTES (LSA_CAP*12 + LSA_CAP/8)  // 220384

// ------------------- scratch (device globals; no runtime allocation) -------------------
__device__ float  d_cost[N_GT][N_PRED];   // 32MB  cost_T[g][p]
__device__ float  d_giou[N_GT][N_PRED];   // 32MB  giou_T[g][p]
__device__ float  d_maxg[N_GT];
__device__ int    d_order[N_GT];
__device__ int    d_labels[N_GT];

__device__ int    d_ccand_idx[N_GT][CAND_C];  // orig col -> compact id after k_remap
__device__ float  d_ccand_val[N_GT][CAND_C];
__device__ int    d_ccand_cnt[N_GT];

__device__ int    d_gcand_idx[N_GT][GC_NEED];
__device__ int    d_gcand_cnt[N_GT];

__device__ unsigned d_colbm[NBMW];
__device__ int    d_cbase[NBMW];
__device__ int    d_nK;
__device__ int    d_rev[N_PRED];          // compact id -> orig col

// fallback LSA state (global, compact-indexed)
__device__ double d_v[N_PRED];
__device__ double d_shortest[N_PRED];
__device__ int    d_path[N_PRED];
__device__ int    d_stampA[N_PRED];
__device__ int    d_stampSC[N_PRED];
__device__ int    d_row4col[N_PRED];
__device__ int    d_col4row[N_GT];        // final ORIG pred idx per gt
__device__ int    d_Tg[N_GT * CAND_C];

// monotonic ascending key for float
__device__ __forceinline__ unsigned fkey(float f) {
    unsigned u = __float_as_uint(f);
    return (u & 0x80000000u) ? ~u : (u | 0x80000000u);
}

// ------------------- labels decode + bitmap zero -------------------
__global__ void k_labels(const void* lab) {
    __shared__ int is32;
    if (threadIdx.x == 0) {
        const unsigned long long* p = (const unsigned long long*)lab;
        int f = 0;
        for (int i = 0; i < 64; i++) { if (p[i] >> 32) { f = 1; break; } }
        is32 = f;
    }
    __syncthreads();
    int t = threadIdx.x;
    if (t < N_GT) {
        long long v;
        if (is32) v = (long long)((const int*)lab)[t];
        else      v = ((const long long*)lab)[t];
        int iv = (int)v;
        if (iv < 0) iv = 0;
        if (iv >= N_CLS) iv = N_CLS - 1;
        d_labels[t] = iv;
    }
    for (int i = t; i < NBMW; i += blockDim.x) d_colbm[i] = 0u;
}

// ------------------- cost + giou matrices (precise, unfused fp32 — validated) ----------
__global__ void k_cost(const float* __restrict__ pc, const float* __restrict__ ps,
                       const float* __restrict__ cls,
                       const float* __restrict__ gc, const float* __restrict__ gs) {
    __shared__ float glo0[N_GT], glo1[N_GT], glo2[N_GT];
    __shared__ float ghi0[N_GT], ghi1[N_GT], ghi2[N_GT];
    __shared__ float gvol[N_GT];
    __shared__ int   glab[N_GT];
    int t = threadIdx.x;  // blockDim = 128
    {
        float c0 = gc[t*3+0], c1 = gc[t*3+1], c2 = gc[t*3+2];
        float s0 = gs[t*3+0], s1 = gs[t*3+1], s2 = gs[t*3+2];
        float h0s = __fmul_rn(s0, 0.5f), h1s = __fmul_rn(s1, 0.5f), h2s = __fmul_rn(s2, 0.5f);
        float l0 = __fsub_rn(c0, h0s), l1 = __fsub_rn(c1, h1s), l2 = __fsub_rn(c2, h2s);
        float h0 = __fadd_rn(c0, h0s), h1 = __fadd_rn(c1, h1s), h2 = __fadd_rn(c2, h2s);
        glo0[t]=l0; glo1[t]=l1; glo2[t]=l2; ghi0[t]=h0; ghi1[t]=h1; ghi2[t]=h2;
        gvol[t] = __fmul_rn(__fmul_rn(__fsub_rn(h0,l0), __fsub_rn(h1,l1)), __fsub_rn(h2,l2));
        glab[t] = d_labels[t];
    }
    __syncthreads();
    int p = blockIdx.x * blockDim.x + t;
    float c0 = pc[p*3+0], c1 = pc[p*3+1], c2 = pc[p*3+2];
    float s0 = ps[p*3+0], s1 = ps[p*3+1], s2 = ps[p*3+2];
    float h0s = __fmul_rn(s0, 0.5f), h1s = __fmul_rn(s1, 0.5f), h2s = __fmul_rn(s2, 0.5f);
    float pl0 = __fsub_rn(c0, h0s), pl1 = __fsub_rn(c1, h1s), pl2 = __fsub_rn(c2, h2s);
    float ph0 = __fadd_rn(c0, h0s), ph1 = __fadd_rn(c1, h1s), ph2 = __fadd_rn(c2, h2s);
    float vol1 = __fmul_rn(__fmul_rn(__fsub_rn(ph0,pl0), __fsub_rn(ph1,pl1)), __fsub_rn(ph2,pl2));
    const float* clsrow = cls + (size_t)p * N_CLS;

    #pragma unroll 4
    for (int g = 0; g < N_GT; g++) {
        float d0 = fmaxf(__fsub_rn(fminf(ph0, ghi0[g]), fmaxf(pl0, glo0[g])), 0.f);
        float d1 = fmaxf(__fsub_rn(fminf(ph1, ghi1[g]), fmaxf(pl1, glo1[g])), 0.f);
        float d2 = fmaxf(__fsub_rn(fminf(ph2, ghi2[g]), fmaxf(pl2, glo2[g])), 0.f);
        float ov = __fmul_rn(__fmul_rn(d0, d1), d2);
        float un = fmaxf(__fsub_rn(__fadd_rn(vol1, gvol[g]), ov), GEPS);
        float iou = __fdiv_rn(ov, un);
        float e0 = fmaxf(__fsub_rn(fmaxf(ph0, ghi0[g]), fminf(pl0, glo0[g])), 0.f);
        float e1 = fmaxf(__fsub_rn(fmaxf(ph1, ghi1[g]), fminf(pl1, glo1[g])), 0.f);
        float e2 = fmaxf(__fsub_rn(fmaxf(ph2, ghi2[g]), fminf(pl2, glo2[g])), 0.f);
        float enc = fmaxf(__fmul_rn(__fmul_rn(e0, e1), e2), GEPS);
        float gi = __fsub_rn(iou, __fdiv_rn(__fsub_rn(enc, un), enc));
        float cv = __ldg(clsrow + glab[g]);
        float sig = __fdiv_rn(1.0f, __fadd_rn(1.0f, expf(-cv)));
        d_giou[g][p] = gi;
        d_cost[g][p] = __fadd_rn(-sig, __fmul_rn(-2.0f, gi));
    }
}

// ------------------- merged selection: blocks 0..127 cost top-128, 128..255 giou top ----
__global__ void k_select() {
    int b = blockIdx.x, tid = threadIdx.x, nth = blockDim.x;  // nth=256
    __shared__ unsigned hist[256];
    __shared__ unsigned s_pfx;
    __shared__ int s_need, s_all, s_cnt;
    __shared__ float redf[256];

    if (b < N_GT) {
        // ---- cost row: 128 smallest (superset incl. ties at 24-bit prefix) ----
        int row = b;
        if (tid == 0) { s_pfx = 0; s_need = 128; }
        for (int l = 0; l < 3; l++) {
            for (int bb = tid; bb < 256; bb += nth) hist[bb] = 0;
            __syncthreads();
            unsigned pfx = s_pfx;
            for (int j = tid; j < N_PRED; j += nth) {
                unsigned k = fkey(d_cost[row][j]);
                bool ok = (l == 0) || ((k >> (32 - 8 * l)) == pfx);
                if (ok) atomicAdd(&hist[(k >> (24 - 8 * l)) & 255u], 1u);
            }
            __syncthreads();
            if (tid == 0) {
                int need = s_need; unsigned cum = 0; int bb = 0;
                for (; bb < 255; bb++) { if (cum + hist[bb] >= (unsigned)need) break; cum += hist[bb]; }
                s_need = need - (int)cum;
                s_pfx = (s_pfx << 8) | (unsigned)bb;
            }
            __syncthreads();
        }
        if (tid == 0) s_cnt = 0;
        __syncthreads();
        unsigned pfx24 = s_pfx;
        for (int j = tid; j < N_PRED; j += nth) {
            float v = d_cost[row][j];
            unsigned k = fkey(v);
            if ((k >> 8) <= pfx24) {
                int slot = atomicAdd(&s_cnt, 1);
                if (slot < CAND_C) {
                    d_ccand_idx[row][slot] = j;
                    d_ccand_val[row][slot] = v;
                    atomicOr(&d_colbm[j >> 5], 1u << (j & 31));
                }
            }
        }
        __syncthreads();
        if (tid == 0) d_ccand_cnt[row] = (s_cnt < CAND_C) ? s_cnt : CAND_C;
    } else {
        // ---- giou row: top-GC_NEED (>thres) exact-sorted, plus row max ----
        int row = b - N_GT;
        __shared__ unsigned long long buf[GC_CAP];
        if (tid == 0) { s_pfx = 0; s_need = GC_NEED; s_all = 0; }
        float lmax = -1e30f;
        // level 0 (also computes max over ALL values)
        for (int bb = tid; bb < 256; bb += nth) hist[bb] = 0;
        __syncthreads();
        for (int j = tid; j < N_PRED; j += nth) {
            float g = d_giou[row][j];
            lmax = fmaxf(lmax, g);
            if (!(g > IOU_THRES)) continue;
            unsigned k = ~fkey(g);
            atomicAdd(&hist[(k >> 24) & 255u], 1u);
        }
        redf[tid] = lmax;
        __syncthreads();
        for (int off = nth >> 1; off > 0; off >>= 1) {
            if (tid < off) redf[tid] = fmaxf(redf[tid], redf[tid + off]);
            __syncthreads();
        }
        if (tid == 0) {
            d_maxg[row] = redf[0];
            unsigned tot = 0;
            for (int bb = 0; bb < 256; bb++) tot += hist[bb];
            if (tot <= (unsigned)GC_NEED) s_all = 1;
            else {
                int need = s_need; unsigned cum = 0; int bb = 0;
                for (; bb < 255; bb++) { if (cum + hist[bb] >= (unsigned)need) break; cum += hist[bb]; }
                s_need = need - (int)cum;
                s_pfx = (unsigned)bb;
            }
        }
        __syncthreads();
        if (!s_all) {
            for (int l = 1; l < 3; l++) {
                for (int bb = tid; bb < 256; bb += nth) hist[bb] = 0;
                __syncthreads();
                unsigned pfx = s_pfx;
                for (int j = tid; j < N_PRED; j += nth) {
                    float g = d_giou[row][j];
                    if (!(g > IOU_THRES)) continue;
                    unsigned k = ~fkey(g);
                    if ((k >> (32 - 8 * l)) == pfx)
                        atomicAdd(&hist[(k >> (24 - 8 * l)) & 255u], 1u);
                }
                __syncthreads();
                if (tid == 0) {
                    int need = s_need; unsigned cum = 0; int bb = 0;
                    for (; bb < 255; bb++) { if (cum + hist[bb] >= (unsigned)need) break; cum += hist[bb]; }
                    s_need = need - (int)cum;
                    s_pfx = (s_pfx << 8) | (unsigned)bb;
                }
                __syncthreads();
            }
        }
        for (int i = tid; i < GC_CAP; i += nth) buf[i] = 0xFFFFFFFFFFFFFFFFull;
        if (tid == 0) s_cnt = 0;
        __syncthreads();
        unsigned pfx24 = s_pfx; int all = s_all;
        for (int j = tid; j < N_PRED; j += nth) {
            float g = d_giou[row][j];
            if (!(g > IOU_THRES)) continue;
            unsigned k = ~fkey(g);
            if (all || ((k >> 8) <= pfx24)) {
                int slot = atomicAdd(&s_cnt, 1);
                if (slot < GC_CAP) buf[slot] = ((unsigned long long)k << 32) | (unsigned)j;
            }
        }
        __syncthreads();
        // bitonic sort GC_CAP ascending (=> giou desc, idx asc)
        for (int k = 2; k <= GC_CAP; k <<= 1) {
            for (int j = k >> 1; j > 0; j >>= 1) {
                for (int i = tid; i < GC_CAP; i += nth) {
                    int ixj = i ^ j;
                    if (ixj > i) {
                        bool up = ((i & k) == 0);
                        unsigned long long a = buf[i], bb = buf[ixj];
                        if ((a > bb) == up) { buf[i] = bb; buf[ixj] = a; }
                    }
                }
                __syncthreads();
            }
        }
        int cnt = s_cnt; if (cnt > GC_CAP) cnt = GC_CAP; if (cnt > GC_NEED) cnt = GC_NEED;
        for (int i = tid; i < cnt; i += nth)
            d_gcand_idx[row][i] = (int)(buf[i] & 0xFFFFFFFFull);
        if (tid == 0) d_gcand_cnt[row] = cnt;
    }
}

// ------------------- stable argsort (ascending) of maxg -------------------
__global__ void k_order() {
    __shared__ float v[N_GT];
    int t = threadIdx.x;
    v[t] = d_maxg[t];
    __syncthreads();
    float mv = v[t]; int r = 0;
    for (int j = 0; j < N_GT; j++) {
        float o = v[j];
        if (o < mv || (o == mv && j < t)) r++;
    }
    d_order[r] = t;
}

// ------------------- compact column ids: popc scan over bitmap -------------------
__global__ void k_compact() {   // 1 block, 256 threads; 2048 words, 8 per thread
    __shared__ int tsum[256];
    int tid = threadIdx.x;
    int base = tid * 8;
    int cnts[8]; int s = 0;
    #pragma unroll
    for (int w = 0; w < 8; w++) { cnts[w] = __popc(d_colbm[base + w]); s += cnts[w]; }
    tsum[tid] = s;
    __syncthreads();
    for (int off = 1; off < 256; off <<= 1) {
        int v_ = 0;
        if (tid >= off) v_ = tsum[tid - off];
        __syncthreads();
        tsum[tid] += v_;
        __syncthreads();
    }
    int excl = tsum[tid] - s;
    #pragma unroll
    for (int w = 0; w < 8; w++) { d_cbase[base + w] = excl; excl += cnts[w]; }
    if (tid == 255) d_nK = tsum[255];
}

// ------------------- remap candidates to compact ids + reverse map -------------------
__global__ void k_remap() {
    int row = blockIdx.x;
    int cnt = d_ccand_cnt[row];
    for (int s = threadIdx.x; s < cnt; s += blockDim.x) {
        int j = d_ccand_idx[row][s];
        int w = j >> 5;
        int cid = d_cbase[w] + __popc(d_colbm[w] & ((1u << (j & 31)) - 1u));
        d_ccand_idx[row][s] = cid;
        d_rev[cid] = j;
    }
}

// ------------------- init global LSA state (also used by fallback path) ---------------
__global__ void k_initgl() {
    int i = blockIdx.x * blockDim.x + threadIdx.x;
    if (i < N_PRED) {
        d_v[i] = 0.0; d_stampA[i] = 0; d_stampSC[i] = 0; d_row4col[i] = -1;
    }
}

// ------------------- sparse JV LSA: smem-resident fast path + global fallback ---------
__global__ void k_lsa() {
    extern __shared__ unsigned char dsm[];
    double*   shS  = (double*)dsm;                         // [LSA_CAP] shortest
    uint16_t* shT  = (uint16_t*)(dsm + (size_t)LSA_CAP*8); // [LSA_CAP] touched list
    uint8_t*  shP  = dsm + (size_t)LSA_CAP*10;             // [LSA_CAP] path (row)
    uint8_t*  shR  = dsm + (size_t)LSA_CAP*11;             // [LSA_CAP] row4col (255=free)
    unsigned* shSC = (unsigned*)(dsm + (size_t)LSA_CAP*12);// [LSA_CAP/32] SC bitmap

    __shared__ double u[N_GT];
    __shared__ int SR[N_GT];
    __shared__ int c4r[N_GT];
    __shared__ double rv[256];
    __shared__ int ri[256];
    __shared__ int s_nSR, s_row, s_sink, s_nT;
    __shared__ double s_minval;

    int tid = threadIdx.x, nth = blockDim.x;  // 256
    int nK = d_nK;
    const double DINF = 1e300;

    if (nK <= LSA_CAP) {
        // =============== fast path: all Dijkstra state in smem ===============
        for (int i = tid; i < LSA_CAP; i += nth) shS[i] = DINF;
        for (int i = tid; i < LSA_CAP; i += nth) shR[i] = 0xFF;
        for (int i = tid; i < LSA_CAP/32; i += nth) shSC[i] = 0;
        for (int i = tid; i < N_GT; i += nth) { u[i] = 0.0; c4r[i] = -1; }
        __syncthreads();

        for (int cur = 0; cur < N_GT; cur++) {
            if (tid == 0) { s_nSR = 0; s_row = cur; s_sink = -1; s_nT = 0; s_minval = 0.0; }
            __syncthreads();
            for (int step = 0; step < N_GT; step++) {
                int i = s_row;
                if (tid == 0) SR[s_nSR++] = i;
                double mv0 = s_minval, ui = u[i];
                int cnt = d_ccand_cnt[i];
                for (int s = tid; s < cnt; s += nth) {
                    int jc = d_ccand_idx[i][s];
                    if ((shSC[jc >> 5] >> (jc & 31)) & 1u) continue;
                    double r = ((mv0 + (double)d_ccand_val[i][s]) - ui) - d_v[jc];
                    double old = shS[jc];
                    if (r < old) {
                        if (old == DINF) { int t2 = atomicAdd(&s_nT, 1); shT[t2] = (uint16_t)jc; }
                        shS[jc] = r; shP[jc] = (uint8_t)i;
                    }
                }
                __syncthreads();
                double bv = DINF; int bj = 0x7fffffff;
                int nT = s_nT;
                for (int t2 = tid; t2 < nT; t2 += nth) {
                    int jc = shT[t2];
                    if ((shSC[jc >> 5] >> (jc & 31)) & 1u) continue;
                    double sv = shS[jc];
                    if (sv < bv || (sv == bv && jc < bj)) { bv = sv; bj = jc; }
                }
                rv[tid] = bv; ri[tid] = bj;
                __syncthreads();
                for (int off = nth >> 1; off > 0; off >>= 1) {
                    if (tid < off) {
                        double ov = rv[tid + off]; int oj = ri[tid + off];
                        if (ov < rv[tid] || (ov == rv[tid] && oj < ri[tid])) { rv[tid] = ov; ri[tid] = oj; }
                    }
                    __syncthreads();
                }
                if (tid == 0) {
                    int j = ri[0];
                    if (j >= 0 && j < nK) {
                        s_minval = rv[0];
                        shSC[j >> 5] |= (1u << (j & 31));
                        int r4 = shR[j];
                        if (r4 == 0xFF) s_sink = j; else s_row = r4;
                    } else s_sink = -2;
                }
                __syncthreads();
                if (s_sink != -1) break;
            }
            if (s_sink >= 0) {
                if (tid == 0) {
                    u[cur] += s_minval;
                    for (int k = 1; k < s_nSR; k++) {
                        int i2 = SR[k];
                        u[i2] += s_minval - shS[c4r[i2]];
                    }
                }
                int nT = s_nT; double mv = s_minval;
                for (int t2 = tid; t2 < nT; t2 += nth) {
                    int jc = shT[t2];
                    if ((shSC[jc >> 5] >> (jc & 31)) & 1u) d_v[jc] -= mv - shS[jc];
                }
                __syncthreads();
                if (tid == 0) {
                    int j = s_sink;
                    for (int it = 0; it <= N_GT && j >= 0; it++) {
                        int i2 = shP[j];
                        shR[j] = (uint8_t)i2;
                        int tmp = c4r[i2];
                        c4r[i2] = j;
                        j = tmp;
                        if (i2 == cur) break;
                    }
                }
            }
            __syncthreads();
            // reset touched entries + SC bitmap for next augmentation
            int nT = s_nT;
            for (int t2 = tid; t2 < nT; t2 += nth) shS[shT[t2]] = DINF;
            for (int i = tid; i < (nK + 31) / 32; i += nth) shSC[i] = 0;
            __syncthreads();
        }
        if (tid < N_GT) d_col4row[tid] = d_rev[c4r[tid]];
    } else {
        // =============== fallback path: global state (validated round-4 logic) =========
        for (int i = tid; i < N_GT; i += nth) { u[i] = 0.0; c4r[i] = -1; }
        __syncthreads();
        for (int cur = 0; cur < N_GT; cur++) {
            int stamp = cur + 1;
            if (tid == 0) { s_nSR = 0; s_row = cur; s_sink = -1; s_nT = 0; s_minval = 0.0; }
            __syncthreads();
            for (int step = 0; step < N_GT; step++) {
                int i = s_row;
                if (tid == 0) SR[s_nSR++] = i;
                double mv0 = s_minval, ui = u[i];
                int cnt = d_ccand_cnt[i];
                for (int s = tid; s < cnt; s += nth) {
                    int jc = d_ccand_idx[i][s];
                    if (d_stampSC[jc] == stamp) continue;
                    double r = ((mv0 + (double)d_ccand_val[i][s]) - ui) - d_v[jc];
                    if (d_stampA[jc] != stamp) {
                        d_stampA[jc] = stamp;
                        d_shortest[jc] = r; d_path[jc] = i;
                        int t2 = atomicAdd(&s_nT, 1);
                        d_Tg[t2] = jc;
                    } else if (r < d_shortest[jc]) {
                        d_shortest[jc] = r; d_path[jc] = i;
                    }
                }
                __syncthreads();
                double bv = DINF; int bj = 0x7fffffff;
                int nT = s_nT;
                for (int t2 = tid; t2 < nT; t2 += nth) {
                    int jc = d_Tg[t2];
                    if (d_stampSC[jc] == stamp) continue;
                    double sv = d_shortest[jc];
                    if (sv < bv || (sv == bv && jc < bj)) { bv = sv; bj = jc; }
                }
                rv[tid] = bv; ri[tid] = bj;
                __syncthreads();
                for (int off = nth >> 1; off > 0; off >>= 1) {
                    if (tid < off) {
                        double ov = rv[tid + off]; int oj = ri[tid + off];
                        if (ov < rv[tid] || (ov == rv[tid] && oj < ri[tid])) { rv[tid] = ov; ri[tid] = oj; }
                    }
                    __syncthreads();
                }
                if (tid == 0) {
                    int j = ri[0];
                    if (j >= 0 && j < N_PRED) {
                        s_minval = rv[0];
                        d_stampSC[j] = stamp;
                        if (d_row4col[j] < 0) s_sink = j; else s_row = d_row4col[j];
                    } else s_sink = -2;
                }
                __syncthreads();
                if (s_sink != -1) break;
            }
            if (s_sink >= 0) {
                if (tid == 0) {
                    u[cur] += s_minval;
                    for (int k = 1; k < s_nSR; k++) {
                        int i2 = SR[k];
                        u[i2] += s_minval - d_shortest[c4r[i2]];
                    }
                }
                int nT = s_nT; double mv = s_minval;
                for (int t2 = tid; t2 < nT; t2 += nth) {
                    int jc = d_Tg[t2];
                    if (d_stampSC[jc] == stamp) d_v[jc] -= mv - d_shortest[jc];
                }
                __syncthreads();
                if (tid == 0) {
                    int j = s_sink;
                    for (int it = 0; it <= N_GT && j >= 0; it++) {
                        int i2 = d_path[j];
                        d_row4col[j] = i2;
                        int tmp = c4r[i2];
                        c4r[i2] = j;
                        j = tmp;
                        if (i2 == cur) break;
                    }
                }
            }
            __syncthreads();
        }
        if (tid < N_GT) d_col4row[tid] = d_rev[c4r[tid]];
    }
}

// ------------------- dynamic assignment + float32 output -------------------
__global__ void k_dyn(float* __restrict__ out) {
    __shared__ unsigned used[NBMW];   // 8KB
    __shared__ int res_p[1408];
    __shared__ int res_g[1408];
    __shared__ int pref[N_GT][32];    // 16KB: first 32 candidates per gt
    __shared__ int cnts[N_GT], ordv[N_GT];
    int tid = threadIdx.x;
    for (int i = tid; i < NBMW; i += blockDim.x) used[i] = 0;
    if (tid < N_GT) { cnts[tid] = d_gcand_cnt[tid]; ordv[tid] = d_order[tid]; }
    __syncthreads();
    for (int i = tid; i < N_GT * 32; i += blockDim.x) {
        int g = i >> 5, s = i & 31;
        pref[g][s] = (s < cnts[g]) ? d_gcand_idx[g][s] : -1;
    }
    if (tid < N_GT) {
        int p = d_col4row[tid];
        if (p >= 0 && p < N_PRED) atomicOr(&used[p >> 5], 1u << (p & 31));
        res_p[tid] = p;
        res_g[tid] = tid;
    }
    __syncthreads();
    if (tid < 32) {
        int lane = tid;
        for (int t = 0; t < N_GT; t++) {
            int g = ordv[t];
            int cnt = cnts[g];
            int picked = 0;
            for (int base = 0; base < cnt && picked < MAX_DYN; base += 32) {
                int idx = -1;
                if (base + lane < cnt)
                    idx = (base == 0) ? pref[g][lane] : d_gcand_idx[g][base + lane];
                bool elig = (idx >= 0) && (idx < N_PRED) && !((used[idx >> 5] >> (idx & 31)) & 1u);
                unsigned m = __ballot_sync(0xffffffffu, elig);
                int K = MAX_DYN - picked;
                int pre = __popc(m & ((1u << lane) - 1u));
                if (elig && pre < K) {
                    atomicOr(&used[idx >> 5], 1u << (idx & 31));
                    res_p[128 + t * MAX_DYN + picked + pre] = idx;
                    res_g[128 + t * MAX_DYN + picked + pre] = g;
                }
                int got = __popc(m); if (got > K) got = K;
                picked += got;
                __syncwarp();
            }
            if (lane >= picked && lane < MAX_DYN) {
                res_p[128 + t * MAX_DYN + lane] = -1;
                res_g[128 + t * MAX_DYN + lane] = -1;
            }
            __syncwarp();
        }
    }
    __syncthreads();
    for (int i = tid; i < 1408; i += blockDim.x) {
        out[i]        = (float)res_p[i];
        out[1408 + i] = (float)res_g[i];
    }
}

// ------------------- launch (inputs resolved by element count) -------------------
extern "C" void kernel_launch(void* const* d_in, const int* in_sizes, int n_in,
                              void* d_out, int out_size) {
    const float* all_centers = 0;
    const float* all_sizes   = 0;
    const float* all_cls     = 0;
    const float* gt_centers  = 0;
    const float* gt_sizes    = 0;
    const void*  gt_labels   = 0;
    int seen196 = 0, seen384 = 0;
    for (int i = 0; i < n_in; i++) {
        long long s = in_sizes[i];
        if (s == (long long)N_PRED * N_CLS) {
            all_cls = (const float*)d_in[i];
        } else if (s == (long long)N_PRED * 3) {
            if (seen196++ == 0) all_centers = (const float*)d_in[i];
            else                all_sizes   = (const float*)d_in[i];
        } else if (s == (long long)N_GT * 3) {
            if (seen384++ == 0) gt_centers = (const float*)d_in[i];
            else                gt_sizes   = (const float*)d_in[i];
        } else if (s == (long long)N_GT) {
            gt_labels = d_in[i];
        }
    }

    cudaFuncSetAttribute(k_lsa, cudaFuncAttributeMaxDynamicSharedMemorySize, LSA_DYN_BYTES);

    k_labels<<<1, 128>>>(gt_labels);
    k_cost<<<N_PRED / 128, 128>>>(all_centers, all_sizes, all_cls, gt_centers, gt_sizes);
    k_select<<<2 * N_GT, 256>>>();
    k_order<<<1, N_GT>>>();
    k_compact<<<1, 256>>>();
    k_remap<<<N_GT, 128>>>();
    k_initgl<<<N_PRED / 256, 256>>>();
    k_lsa<<<1, 256, LSA_DYN_BYTES>>>();
    k_dyn<<<1, 256>>>((float*)d_out);
}

// round 6
// speedup vs baseline: 3.1175x; 2.0247x over previous
#include <cuda_runtime.h>
#include <math.h>
#include <stdint.h>

#define N_PRED 65536
#define N_GT   128
#define N_CLS  256
#define MAX_DYN 10
#define GEPS   1e-6f
#define IOU_THRES 0.25f
#define CAND_C 512      // per-row LSA candidate cap (need >=128)
#define GC_NEED 1408    // per-gt dynamic candidate depth (10 + 128 + 10*127)
#define GC_CAP  2048    // collection cap before sort
#define NBMW   (N_PRED/32)   // 2048 bitmap words
#define LSA_CAP 18176        // smem LSA capacity (compact columns)
#define LSA_DYN_BYTES (LSA_CAP*12 + LSA_CAP/8)  // 220384

// ------------------- scratch (device globals; no runtime allocation) -------------------
__device__ float  d_cost[N_GT][N_PRED];   // 32MB  cost_T[g][p]
__device__ float  d_giou[N_GT][N_PRED];   // 32MB  giou_T[g][p]
__device__ float  d_maxg[N_GT];
__device__ int    d_order[N_GT];
__device__ int    d_labels[N_GT];

__device__ int    d_ccand_idx[N_GT][CAND_C];  // orig col -> compact id after k_remap
__device__ float  d_ccand_val[N_GT][CAND_C];
__device__ int    d_ccand_cnt[N_GT];

__device__ int    d_gcand_idx[N_GT][GC_NEED];
__device__ int    d_gcand_cnt[N_GT];

__device__ unsigned d_colbm[NBMW];
__device__ int    d_cbase[NBMW];
__device__ int    d_nK;
__device__ int    d_rev[N_PRED];          // compact id -> orig col

// fallback LSA state (global, compact-indexed)
__device__ double d_v[N_PRED];
__device__ double d_shortest[N_PRED];
__device__ int    d_path[N_PRED];
__device__ int    d_stampA[N_PRED];
__device__ int    d_stampSC[N_PRED];
__device__ int    d_row4col[N_PRED];
__device__ int    d_col4row[N_GT];        // final ORIG pred idx per gt
__device__ int    d_Tg[N_GT * CAND_C];

// monotonic ascending key for float
__device__ __forceinline__ unsigned fkey(float f) {
    unsigned u = __float_as_uint(f);
    return (u & 0x80000000u) ? ~u : (u | 0x80000000u);
}

// ------------------- labels decode + bitmap zero -------------------
__global__ void k_labels(const void* lab) {
    __shared__ int is32;
    if (threadIdx.x == 0) {
        const unsigned long long* p = (const unsigned long long*)lab;
        int f = 0;
        for (int i = 0; i < 64; i++) { if (p[i] >> 32) { f = 1; break; } }
        is32 = f;
    }
    __syncthreads();
    int t = threadIdx.x;
    if (t < N_GT) {
        long long v;
        if (is32) v = (long long)((const int*)lab)[t];
        else      v = ((const long long*)lab)[t];
        int iv = (int)v;
        if (iv < 0) iv = 0;
        if (iv >= N_CLS) iv = N_CLS - 1;
        d_labels[t] = iv;
    }
    for (int i = t; i < NBMW; i += blockDim.x) d_colbm[i] = 0u;
}

// ------------------- cost + giou matrices (precise, unfused fp32 — validated) ----------
__global__ void k_cost(const float* __restrict__ pc, const float* __restrict__ ps,
                       const float* __restrict__ cls,
                       const float* __restrict__ gc, const float* __restrict__ gs) {
    __shared__ float glo0[N_GT], glo1[N_GT], glo2[N_GT];
    __shared__ float ghi0[N_GT], ghi1[N_GT], ghi2[N_GT];
    __shared__ float gvol[N_GT];
    __shared__ int   glab[N_GT];
    int t = threadIdx.x;  // blockDim = 128
    {
        float c0 = gc[t*3+0], c1 = gc[t*3+1], c2 = gc[t*3+2];
        float s0 = gs[t*3+0], s1 = gs[t*3+1], s2 = gs[t*3+2];
        float h0s = __fmul_rn(s0, 0.5f), h1s = __fmul_rn(s1, 0.5f), h2s = __fmul_rn(s2, 0.5f);
        float l0 = __fsub_rn(c0, h0s), l1 = __fsub_rn(c1, h1s), l2 = __fsub_rn(c2, h2s);
        float h0 = __fadd_rn(c0, h0s), h1 = __fadd_rn(c1, h1s), h2 = __fadd_rn(c2, h2s);
        glo0[t]=l0; glo1[t]=l1; glo2[t]=l2; ghi0[t]=h0; ghi1[t]=h1; ghi2[t]=h2;
        gvol[t] = __fmul_rn(__fmul_rn(__fsub_rn(h0,l0), __fsub_rn(h1,l1)), __fsub_rn(h2,l2));
        glab[t] = d_labels[t];
    }
    __syncthreads();
    int p = blockIdx.x * blockDim.x + t;
    float c0 = pc[p*3+0], c1 = pc[p*3+1], c2 = pc[p*3+2];
    float s0 = ps[p*3+0], s1 = ps[p*3+1], s2 = ps[p*3+2];
    float h0s = __fmul_rn(s0, 0.5f), h1s = __fmul_rn(s1, 0.5f), h2s = __fmul_rn(s2, 0.5f);
    float pl0 = __fsub_rn(c0, h0s), pl1 = __fsub_rn(c1, h1s), pl2 = __fsub_rn(c2, h2s);
    float ph0 = __fadd_rn(c0, h0s), ph1 = __fadd_rn(c1, h1s), ph2 = __fadd_rn(c2, h2s);
    float vol1 = __fmul_rn(__fmul_rn(__fsub_rn(ph0,pl0), __fsub_rn(ph1,pl1)), __fsub_rn(ph2,pl2));
    const float* clsrow = cls + (size_t)p * N_CLS;

    #pragma unroll 4
    for (int g = 0; g < N_GT; g++) {
        float d0 = fmaxf(__fsub_rn(fminf(ph0, ghi0[g]), fmaxf(pl0, glo0[g])), 0.f);
        float d1 = fmaxf(__fsub_rn(fminf(ph1, ghi1[g]), fmaxf(pl1, glo1[g])), 0.f);
        float d2 = fmaxf(__fsub_rn(fminf(ph2, ghi2[g]), fmaxf(pl2, glo2[g])), 0.f);
        float ov = __fmul_rn(__fmul_rn(d0, d1), d2);
        float un = fmaxf(__fsub_rn(__fadd_rn(vol1, gvol[g]), ov), GEPS);
        float iou = __fdiv_rn(ov, un);
        float e0 = fmaxf(__fsub_rn(fmaxf(ph0, ghi0[g]), fminf(pl0, glo0[g])), 0.f);
        float e1 = fmaxf(__fsub_rn(fmaxf(ph1, ghi1[g]), fminf(pl1, glo1[g])), 0.f);
        float e2 = fmaxf(__fsub_rn(fmaxf(ph2, ghi2[g]), fminf(pl2, glo2[g])), 0.f);
        float enc = fmaxf(__fmul_rn(__fmul_rn(e0, e1), e2), GEPS);
        float gi = __fsub_rn(iou, __fdiv_rn(__fsub_rn(enc, un), enc));
        float cv = __ldg(clsrow + glab[g]);
        float sig = __fdiv_rn(1.0f, __fadd_rn(1.0f, expf(-cv)));
        d_giou[g][p] = gi;
        d_cost[g][p] = __fadd_rn(-sig, __fmul_rn(-2.0f, gi));
    }
}

// ------------------- merged selection: blocks 0..127 cost top-128, 128..255 giou top ----
__global__ void k_select() {
    int b = blockIdx.x, tid = threadIdx.x, nth = blockDim.x;  // nth=256
    __shared__ unsigned hist[256];
    __shared__ unsigned s_pfx;
    __shared__ int s_need, s_all, s_cnt;
    __shared__ float redf[256];

    if (b < N_GT) {
        // ---- cost row: 128 smallest (superset incl. ties at 24-bit prefix) ----
        int row = b;
        if (tid == 0) { s_pfx = 0; s_need = 128; }
        for (int l = 0; l < 3; l++) {
            for (int bb = tid; bb < 256; bb += nth) hist[bb] = 0;
            __syncthreads();
            unsigned pfx = s_pfx;
            for (int j = tid; j < N_PRED; j += nth) {
                unsigned k = fkey(d_cost[row][j]);
                bool ok = (l == 0) || ((k >> (32 - 8 * l)) == pfx);
                if (ok) atomicAdd(&hist[(k >> (24 - 8 * l)) & 255u], 1u);
            }
            __syncthreads();
            if (tid == 0) {
                int need = s_need; unsigned cum = 0; int bb = 0;
                for (; bb < 255; bb++) { if (cum + hist[bb] >= (unsigned)need) break; cum += hist[bb]; }
                s_need = need - (int)cum;
                s_pfx = (s_pfx << 8) | (unsigned)bb;
            }
            __syncthreads();
        }
        if (tid == 0) s_cnt = 0;
        __syncthreads();
        unsigned pfx24 = s_pfx;
        for (int j = tid; j < N_PRED; j += nth) {
            float v = d_cost[row][j];
            unsigned k = fkey(v);
            if ((k >> 8) <= pfx24) {
                int slot = atomicAdd(&s_cnt, 1);
                if (slot < CAND_C) {
                    d_ccand_idx[row][slot] = j;
                    d_ccand_val[row][slot] = v;
                    atomicOr(&d_colbm[j >> 5], 1u << (j & 31));
                }
            }
        }
        __syncthreads();
        if (tid == 0) d_ccand_cnt[row] = (s_cnt < CAND_C) ? s_cnt : CAND_C;
    } else {
        // ---- giou row: top-GC_NEED (>thres) exact-sorted, plus row max ----
        int row = b - N_GT;
        __shared__ unsigned long long buf[GC_CAP];
        if (tid == 0) { s_pfx = 0; s_need = GC_NEED; s_all = 0; }
        float lmax = -1e30f;
        for (int bb = tid; bb < 256; bb += nth) hist[bb] = 0;
        __syncthreads();
        for (int j = tid; j < N_PRED; j += nth) {
            float g = d_giou[row][j];
            lmax = fmaxf(lmax, g);
            if (!(g > IOU_THRES)) continue;
            unsigned k = ~fkey(g);
            atomicAdd(&hist[(k >> 24) & 255u], 1u);
        }
        redf[tid] = lmax;
        __syncthreads();
        for (int off = nth >> 1; off > 0; off >>= 1) {
            if (tid < off) redf[tid] = fmaxf(redf[tid], redf[tid + off]);
            __syncthreads();
        }
        if (tid == 0) {
            d_maxg[row] = redf[0];
            unsigned tot = 0;
            for (int bb = 0; bb < 256; bb++) tot += hist[bb];
            if (tot <= (unsigned)GC_NEED) s_all = 1;
            else {
                int need = s_need; unsigned cum = 0; int bb = 0;
                for (; bb < 255; bb++) { if (cum + hist[bb] >= (unsigned)need) break; cum += hist[bb]; }
                s_need = need - (int)cum;
                s_pfx = (unsigned)bb;
            }
        }
        __syncthreads();
        if (!s_all) {
            for (int l = 1; l < 3; l++) {
                for (int bb = tid; bb < 256; bb += nth) hist[bb] = 0;
                __syncthreads();
                unsigned pfx = s_pfx;
                for (int j = tid; j < N_PRED; j += nth) {
                    float g = d_giou[row][j];
                    if (!(g > IOU_THRES)) continue;
                    unsigned k = ~fkey(g);
                    if ((k >> (32 - 8 * l)) == pfx)
                        atomicAdd(&hist[(k >> (24 - 8 * l)) & 255u], 1u);
                }
                __syncthreads();
                if (tid == 0) {
                    int need = s_need; unsigned cum = 0; int bb = 0;
                    for (; bb < 255; bb++) { if (cum + hist[bb] >= (unsigned)need) break; cum += hist[bb]; }
                    s_need = need - (int)cum;
                    s_pfx = (s_pfx << 8) | (unsigned)bb;
                }
                __syncthreads();
            }
        }
        for (int i = tid; i < GC_CAP; i += nth) buf[i] = 0xFFFFFFFFFFFFFFFFull;
        if (tid == 0) s_cnt = 0;
        __syncthreads();
        unsigned pfx24 = s_pfx; int all = s_all;
        for (int j = tid; j < N_PRED; j += nth) {
            float g = d_giou[row][j];
            if (!(g > IOU_THRES)) continue;
            unsigned k = ~fkey(g);
            if (all || ((k >> 8) <= pfx24)) {
                int slot = atomicAdd(&s_cnt, 1);
                if (slot < GC_CAP) buf[slot] = ((unsigned long long)k << 32) | (unsigned)j;
            }
        }
        __syncthreads();
        for (int k = 2; k <= GC_CAP; k <<= 1) {
            for (int j = k >> 1; j > 0; j >>= 1) {
                for (int i = tid; i < GC_CAP; i += nth) {
                    int ixj = i ^ j;
                    if (ixj > i) {
                        bool up = ((i & k) == 0);
                        unsigned long long a = buf[i], bb = buf[ixj];
                        if ((a > bb) == up) { buf[i] = bb; buf[ixj] = a; }
                    }
                }
                __syncthreads();
            }
        }
        int cnt = s_cnt; if (cnt > GC_CAP) cnt = GC_CAP; if (cnt > GC_NEED) cnt = GC_NEED;
        for (int i = tid; i < cnt; i += nth)
            d_gcand_idx[row][i] = (int)(buf[i] & 0xFFFFFFFFull);
        if (tid == 0) d_gcand_cnt[row] = cnt;
    }
}

// ------------------- stable argsort (ascending) of maxg -------------------
__global__ void k_order() {
    __shared__ float v[N_GT];
    int t = threadIdx.x;
    v[t] = d_maxg[t];
    __syncthreads();
    float mv = v[t]; int r = 0;
    for (int j = 0; j < N_GT; j++) {
        float o = v[j];
        if (o < mv || (o == mv && j < t)) r++;
    }
    d_order[r] = t;
}

// ------------------- compact column ids: popc scan over bitmap -------------------
__global__ void k_compact() {   // 1 block, 256 threads; 2048 words, 8 per thread
    __shared__ int tsum[256];
    int tid = threadIdx.x;
    int base = tid * 8;
    int cnts[8]; int s = 0;
    #pragma unroll
    for (int w = 0; w < 8; w++) { cnts[w] = __popc(d_colbm[base + w]); s += cnts[w]; }
    tsum[tid] = s;
    __syncthreads();
    for (int off = 1; off < 256; off <<= 1) {
        int v_ = 0;
        if (tid >= off) v_ = tsum[tid - off];
        __syncthreads();
        tsum[tid] += v_;
        __syncthreads();
    }
    int excl = tsum[tid] - s;
    #pragma unroll
    for (int w = 0; w < 8; w++) { d_cbase[base + w] = excl; excl += cnts[w]; }
    if (tid == 255) d_nK = tsum[255];
}

// ------------------- remap candidates to compact ids + reverse map -------------------
__global__ void k_remap() {
    int row = blockIdx.x;
    int cnt = d_ccand_cnt[row];
    for (int s = threadIdx.x; s < cnt; s += blockDim.x) {
        int j = d_ccand_idx[row][s];
        int w = j >> 5;
        int cid = d_cbase[w] + __popc(d_colbm[w] & ((1u << (j & 31)) - 1u));
        d_ccand_idx[row][s] = cid;
        d_rev[cid] = j;
    }
}

// ------------------- init global LSA state (fallback + v) ---------------
__global__ void k_initgl() {
    int i = blockIdx.x * blockDim.x + threadIdx.x;
    if (i < N_PRED) {
        d_v[i] = 0.0; d_stampA[i] = 0; d_stampSC[i] = 0; d_row4col[i] = -1;
    }
}

// ------------------- sparse JV LSA: greedy tight init + rare augmentations ------------
__global__ void k_lsa() {
    extern __shared__ unsigned char dsm[];
    double*   shS  = (double*)dsm;                         // [LSA_CAP] shortest
    uint16_t* shT  = (uint16_t*)(dsm + (size_t)LSA_CAP*8); // [LSA_CAP] touched list
    uint8_t*  shP  = dsm + (size_t)LSA_CAP*10;             // [LSA_CAP] path (row)
    uint8_t*  shR  = dsm + (size_t)LSA_CAP*11;             // [LSA_CAP] row4col (255=free)
    unsigned* shSC = (unsigned*)(dsm + (size_t)LSA_CAP*12);// [LSA_CAP/32] SC bitmap

    __shared__ double u[N_GT];
    __shared__ int SR[N_GT];
    __shared__ int c4r[N_GT];
    __shared__ float rminf[N_GT];
    __shared__ int   rarg[N_GT];
    __shared__ int   pend[N_GT];
    __shared__ double rv[256];
    __shared__ int ri[256];
    __shared__ int s_nSR, s_row, s_sink, s_nT, s_npend;
    __shared__ double s_minval;

    int tid = threadIdx.x, nth = blockDim.x;  // 256
    int nK = d_nK;
    const double DINF = 1e300;

    if (nK <= LSA_CAP) {
        // ---- init smem state ----
        for (int i = tid; i < LSA_CAP; i += nth) shS[i] = DINF;
        for (int i = tid; i < LSA_CAP; i += nth) shR[i] = 0xFF;
        for (int i = tid; i < LSA_CAP/32; i += nth) shSC[i] = 0;
        for (int i = tid; i < N_GT; i += nth) c4r[i] = -1;
        __syncthreads();

        // ---- stage 1: per-row argmin over candidates (warp per row) ----
        {
            int w = tid >> 5, lane = tid & 31;
            for (int i = w; i < N_GT; i += 8) {
                int cnt = d_ccand_cnt[i];
                float bv = 1e30f; int bj = 0x7fffffff;
                for (int s = lane; s < cnt; s += 32) {
                    float v_ = d_ccand_val[i][s];
                    int j = d_ccand_idx[i][s];
                    if (v_ < bv || (v_ == bv && j < bj)) { bv = v_; bj = j; }
                }
                #pragma unroll
                for (int off = 16; off > 0; off >>= 1) {
                    float ov = __shfl_down_sync(0xffffffffu, bv, off);
                    int   oj = __shfl_down_sync(0xffffffffu, bj, off);
                    if (ov < bv || (ov == bv && oj < bj)) { bv = ov; bj = oj; }
                }
                if (lane == 0) { rminf[i] = bv; rarg[i] = bj; }
            }
        }
        __syncthreads();

        // ---- stage 2: greedy tight assignment (u[i] = row min, v = 0) ----
        if (tid == 0) {
            s_npend = 0;
            for (int i = 0; i < N_GT; i++) {
                u[i] = (double)rminf[i];
                int j = rarg[i];
                if (j >= 0 && j < nK && shR[j] == 0xFF) {
                    shR[j] = (uint8_t)i; c4r[i] = j;
                } else {
                    pend[s_npend++] = i;
                }
            }
        }
        __syncthreads();
        int npend = s_npend;

        // ---- stage 3: shortest augmenting path for each conflicted row ----
        for (int pi = 0; pi < npend; pi++) {
            int cur = pend[pi];
            if (tid == 0) { s_nSR = 0; s_row = cur; s_sink = -1; s_nT = 0; s_minval = 0.0; }
            __syncthreads();
            for (int step = 0; step < N_GT; step++) {
                int i = s_row;
                if (tid == 0) SR[s_nSR++] = i;
                double mv0 = s_minval, ui = u[i];
                int cnt = d_ccand_cnt[i];
                for (int s = tid; s < cnt; s += nth) {
                    int jc = d_ccand_idx[i][s];
                    if ((shSC[jc >> 5] >> (jc & 31)) & 1u) continue;
                    double r = ((mv0 + (double)d_ccand_val[i][s]) - ui) - d_v[jc];
                    double old = shS[jc];
                    if (r < old) {
                        if (old == DINF) { int t2 = atomicAdd(&s_nT, 1); shT[t2] = (uint16_t)jc; }
                        shS[jc] = r; shP[jc] = (uint8_t)i;
                    }
                }
                __syncthreads();
                double bv = DINF; int bj = 0x7fffffff;
                int nT = s_nT;
                for (int t2 = tid; t2 < nT; t2 += nth) {
                    int jc = shT[t2];
                    if ((shSC[jc >> 5] >> (jc & 31)) & 1u) continue;
                    double sv = shS[jc];
                    if (sv < bv || (sv == bv && jc < bj)) { bv = sv; bj = jc; }
                }
                rv[tid] = bv; ri[tid] = bj;
                __syncthreads();
                for (int off = nth >> 1; off > 0; off >>= 1) {
                    if (tid < off) {
                        double ov = rv[tid + off]; int oj = ri[tid + off];
                        if (ov < rv[tid] || (ov == rv[tid] && oj < ri[tid])) { rv[tid] = ov; ri[tid] = oj; }
                    }
                    __syncthreads();
                }
                if (tid == 0) {
                    int j = ri[0];
                    if (j >= 0 && j < nK) {
                        s_minval = rv[0];
                        shSC[j >> 5] |= (1u << (j & 31));
                        int r4 = shR[j];
                        if (r4 == 0xFF) s_sink = j; else s_row = r4;
                    } else s_sink = -2;
                }
                __syncthreads();
                if (s_sink != -1) break;
            }
            if (s_sink >= 0) {
                if (tid == 0) {
                    u[cur] += s_minval;
                    for (int k = 1; k < s_nSR; k++) {
                        int i2 = SR[k];
                        u[i2] += s_minval - shS[c4r[i2]];
                    }
                }
                int nT = s_nT; double mv = s_minval;
                for (int t2 = tid; t2 < nT; t2 += nth) {
                    int jc = shT[t2];
                    if ((shSC[jc >> 5] >> (jc & 31)) & 1u) d_v[jc] -= mv - shS[jc];
                }
                __syncthreads();
                if (tid == 0) {
                    int j = s_sink;
                    for (int it = 0; it <= N_GT && j >= 0; it++) {
                        int i2 = shP[j];
                        shR[j] = (uint8_t)i2;
                        int tmp = c4r[i2];
                        c4r[i2] = j;
                        j = tmp;
                        if (i2 == cur) break;
                    }
                }
            }
            __syncthreads();
            // reset touched + SC for next augmentation
            int nT = s_nT;
            for (int t2 = tid; t2 < nT; t2 += nth) shS[shT[t2]] = DINF;
            for (int i = tid; i < (nK + 31) / 32; i += nth) shSC[i] = 0;
            __syncthreads();
        }
        if (tid < N_GT) d_col4row[tid] = d_rev[c4r[tid]];
    } else {
        // =============== fallback path: global state (validated round-4 logic) =========
        for (int i = tid; i < N_GT; i += nth) { u[i] = 0.0; c4r[i] = -1; }
        __syncthreads();
        for (int cur = 0; cur < N_GT; cur++) {
            int stamp = cur + 1;
            if (tid == 0) { s_nSR = 0; s_row = cur; s_sink = -1; s_nT = 0; s_minval = 0.0; }
            __syncthreads();
            for (int step = 0; step < N_GT; step++) {
                int i = s_row;
                if (tid == 0) SR[s_nSR++] = i;
                double mv0 = s_minval, ui = u[i];
                int cnt = d_ccand_cnt[i];
                for (int s = tid; s < cnt; s += nth) {
                    int jc = d_ccand_idx[i][s];
                    if (d_stampSC[jc] == stamp) continue;
                    double r = ((mv0 + (double)d_ccand_val[i][s]) - ui) - d_v[jc];
                    if (d_stampA[jc] != stamp) {
                        d_stampA[jc] = stamp;
                        d_shortest[jc] = r; d_path[jc] = i;
                        int t2 = atomicAdd(&s_nT, 1);
                        d_Tg[t2] = jc;
                    } else if (r < d_shortest[jc]) {
                        d_shortest[jc] = r; d_path[jc] = i;
                    }
                }
                __syncthreads();
                double bv = DINF; int bj = 0x7fffffff;
                int nT = s_nT;
                for (int t2 = tid; t2 < nT; t2 += nth) {
                    int jc = d_Tg[t2];
                    if (d_stampSC[jc] == stamp) continue;
                    double sv = d_shortest[jc];
                    if (sv < bv || (sv == bv && jc < bj)) { bv = sv; bj = jc; }
                }
                rv[tid] = bv; ri[tid] = bj;
                __syncthreads();
                for (int off = nth >> 1; off > 0; off >>= 1) {
                    if (tid < off) {
                        double ov = rv[tid + off]; int oj = ri[tid + off];
                        if (ov < rv[tid] || (ov == rv[tid] && oj < ri[tid])) { rv[tid] = ov; ri[tid] = oj; }
                    }
                    __syncthreads();
                }
                if (tid == 0) {
                    int j = ri[0];
                    if (j >= 0 && j < N_PRED) {
                        s_minval = rv[0];
                        d_stampSC[j] = stamp;
                        if (d_row4col[j] < 0) s_sink = j; else s_row = d_row4col[j];
                    } else s_sink = -2;
                }
                __syncthreads();
                if (s_sink != -1) break;
            }
            if (s_sink >= 0) {
                if (tid == 0) {
                    u[cur] += s_minval;
                    for (int k = 1; k < s_nSR; k++) {
                        int i2 = SR[k];
                        u[i2] += s_minval - d_shortest[c4r[i2]];
                    }
                }
                int nT = s_nT; double mv = s_minval;
                for (int t2 = tid; t2 < nT; t2 += nth) {
                    int jc = d_Tg[t2];
                    if (d_stampSC[jc] == stamp) d_v[jc] -= mv - d_shortest[jc];
                }
                __syncthreads();
                if (tid == 0) {
                    int j = s_sink;
                    for (int it = 0; it <= N_GT && j >= 0; it++) {
                        int i2 = d_path[j];
                        d_row4col[j] = i2;
                        int tmp = c4r[i2];
                        c4r[i2] = j;
                        j = tmp;
                        if (i2 == cur) break;
                    }
                }
            }
            __syncthreads();
        }
        if (tid < N_GT) d_col4row[tid] = d_rev[c4r[tid]];
    }
}

// ------------------- dynamic assignment + float32 output -------------------
__global__ void k_dyn(float* __restrict__ out) {
    __shared__ unsigned used[NBMW];   // 8KB
    __shared__ int res_p[1408];
    __shared__ int res_g[1408];
    __shared__ int pref[N_GT][32];    // 16KB: first 32 candidates per gt
    __shared__ int cnts[N_GT], ordv[N_GT];
    int tid = threadIdx.x;
    for (int i = tid; i < NBMW; i += blockDim.x) used[i] = 0;
    if (tid < N_GT) { cnts[tid] = d_gcand_cnt[tid]; ordv[tid] = d_order[tid]; }
    __syncthreads();
    for (int i = tid; i < N_GT * 32; i += blockDim.x) {
        int g = i >> 5, s = i & 31;
        pref[g][s] = (s < cnts[g]) ? d_gcand_idx[g][s] : -1;
    }
    if (tid < N_GT) {
        int p = d_col4row[tid];
        if (p >= 0 && p < N_PRED) atomicOr(&used[p >> 5], 1u << (p & 31));
        res_p[tid] = p;
        res_g[tid] = tid;
    }
    __syncthreads();
    if (tid < 32) {
        int lane = tid;
        for (int t = 0; t < N_GT; t++) {
            int g = ordv[t];
            int cnt = cnts[g];
            int picked = 0;
            for (int base = 0; base < cnt && picked < MAX_DYN; base += 32) {
                int idx = -1;
                if (base + lane < cnt)
                    idx = (base == 0) ? pref[g][lane] : d_gcand_idx[g][base + lane];
                bool elig = (idx >= 0) && (idx < N_PRED) && !((used[idx >> 5] >> (idx & 31)) & 1u);
                unsigned m = __ballot_sync(0xffffffffu, elig);
                int K = MAX_DYN - picked;
                int pre = __popc(m & ((1u << lane) - 1u));
                if (elig && pre < K) {
                    atomicOr(&used[idx >> 5], 1u << (idx & 31));
                    res_p[128 + t * MAX_DYN + picked + pre] = idx;
                    res_g[128 + t * MAX_DYN + picked + pre] = g;
                }
                int got = __popc(m); if (got > K) got = K;
                picked += got;
                __syncwarp();
            }
            if (lane >= picked && lane < MAX_DYN) {
                res_p[128 + t * MAX_DYN + lane] = -1;
                res_g[128 + t * MAX_DYN + lane] = -1;
            }
            __syncwarp();
        }
    }
    __syncthreads();
    for (int i = tid; i < 1408; i += blockDim.x) {
        out[i]        = (float)res_p[i];
        out[1408 + i] = (float)res_g[i];
    }
}

// ------------------- launch (inputs resolved by element count) -------------------
extern "C" void kernel_launch(void* const* d_in, const int* in_sizes, int n_in,
                              void* d_out, int out_size) {
    const float* all_centers = 0;
    const float* all_sizes   = 0;
    const float* all_cls     = 0;
    const float* gt_centers  = 0;
    const float* gt_sizes    = 0;
    const void*  gt_labels   = 0;
    int seen196 = 0, seen384 = 0;
    for (int i = 0; i < n_in; i++) {
        long long s = in_sizes[i];
        if (s == (long long)N_PRED * N_CLS) {
            all_cls = (const float*)d_in[i];
        } else if (s == (long long)N_PRED * 3) {
            if (seen196++ == 0) all_centers = (const float*)d_in[i];
            else                all_sizes   = (const float*)d_in[i];
        } else if (s == (long long)N_GT * 3) {
            if (seen384++ == 0) gt_centers = (const float*)d_in[i];
            else                gt_sizes   = (const float*)d_in[i];
        } else if (s == (long long)N_GT) {
            gt_labels = d_in[i];
        }
    }

    cudaFuncSetAttribute(k_lsa, cudaFuncAttributeMaxDynamicSharedMemorySize, LSA_DYN_BYTES);

    k_labels<<<1, 128>>>(gt_labels);
    k_cost<<<N_PRED / 128, 128>>>(all_centers, all_sizes, all_cls, gt_centers, gt_sizes);
    k_select<<<2 * N_GT, 256>>>();
    k_order<<<1, N_GT>>>();
    k_compact<<<1, 256>>>();
    k_remap<<<N_GT, 128>>>();
    k_initgl<<<N_PRED / 256, 256>>>();
    k_lsa<<<1, 256, LSA_DYN_BYTES>>>();
    k_dyn<<<1, 256>>>((float*)d_out);
}

// round 7
// speedup vs baseline: 3.8923x; 1.2485x over previous
#include <cuda_runtime.h>
#include <math.h>
#include <stdint.h>

#define N_PRED 65536
#define N_GT   128
#define N_CLS  256
#define MAX_DYN 10
#define GEPS   1e-6f
#define IOU_THRES 0.25f
#define CAND_C 128      // per-row LSA candidates: exactly the 128 smallest
#define SEL_CAP 4096    // collection buffer cap (smem)
#define GC_NEED 1408    // per-gt dynamic candidate depth (10 + 128 + 10*127)
#define NBMW   (N_PRED/32)   // 2048 bitmap words
#define LSA_CAP 18176        // smem LSA capacity (compact columns); union <= 128*128=16384
#define LSA_DYN_BYTES (LSA_CAP*12 + LSA_CAP/8)  // 220384

typedef unsigned long long ull;

// ------------------- scratch (device globals; no runtime allocation) -------------------
__device__ float  d_cost[N_GT][N_PRED];   // 32MB  cost_T[g][p]
__device__ float  d_giou[N_GT][N_PRED];   // 32MB  giou_T[g][p]
__device__ float  d_maxg[N_GT];
__device__ int    d_order[N_GT];
__device__ int    d_labels[N_GT];

__device__ int    d_ccand_idx[N_GT][CAND_C];  // sorted by (cost,idx) asc; remapped to compact ids
__device__ float  d_ccand_val[N_GT][CAND_C];
__device__ int    d_ccand_cnt[N_GT];

__device__ int    d_gcand_idx[N_GT][GC_NEED];
__device__ int    d_gcand_cnt[N_GT];

__device__ unsigned d_colbm[NBMW];
__device__ int    d_cbase[NBMW];
__device__ int    d_nK;
__device__ int    d_rev[N_PRED];          // compact id -> orig col

// fallback LSA state (global, compact-indexed)
__device__ double d_v[N_PRED];
__device__ double d_shortest[N_PRED];
__device__ int    d_path[N_PRED];
__device__ int    d_stampA[N_PRED];
__device__ int    d_stampSC[N_PRED];
__device__ int    d_row4col[N_PRED];
__device__ int    d_col4row[N_GT];        // final ORIG pred idx per gt
__device__ int    d_Tg[N_GT * CAND_C];

// monotonic ascending key for float
__device__ __forceinline__ unsigned fkey(float f) {
    unsigned u = __float_as_uint(f);
    return (u & 0x80000000u) ? ~u : (u | 0x80000000u);
}

// block bitonic sort, ascending, n = power of two, all threads participate
__device__ __forceinline__ void bsort(ull* a, int n, int tid, int nth) {
    for (int k = 2; k <= n; k <<= 1) {
        for (int j = k >> 1; j > 0; j >>= 1) {
            for (int i = tid; i < n; i += nth) {
                int ixj = i ^ j;
                if (ixj > i) {
                    bool up = ((i & k) == 0);
                    ull x = a[i], y = a[ixj];
                    if ((x > y) == up) { a[i] = y; a[ixj] = x; }
                }
            }
            __syncthreads();
        }
    }
}

// ------------------- labels decode + bitmap zero -------------------
__global__ void k_labels(const void* lab) {
    __shared__ int is32;
    if (threadIdx.x == 0) {
        const ull* p = (const ull*)lab;
        int f = 0;
        for (int i = 0; i < 64; i++) { if (p[i] >> 32) { f = 1; break; } }
        is32 = f;
    }
    __syncthreads();
    int t = threadIdx.x;
    if (t < N_GT) {
        long long v;
        if (is32) v = (long long)((const int*)lab)[t];
        else      v = ((const long long*)lab)[t];
        int iv = (int)v;
        if (iv < 0) iv = 0;
        if (iv >= N_CLS) iv = N_CLS - 1;
        d_labels[t] = iv;
    }
    for (int i = t; i < NBMW; i += blockDim.x) d_colbm[i] = 0u;
}

// ------------------- cost + giou matrices (precise, unfused fp32 — validated) ----------
__global__ void k_cost(const float* __restrict__ pc, const float* __restrict__ ps,
                       const float* __restrict__ cls,
                       const float* __restrict__ gc, const float* __restrict__ gs) {
    __shared__ float glo0[N_GT], glo1[N_GT], glo2[N_GT];
    __shared__ float ghi0[N_GT], ghi1[N_GT], ghi2[N_GT];
    __shared__ float gvol[N_GT];
    __shared__ int   glab[N_GT];
    int t = threadIdx.x;  // blockDim = 128
    {
        float c0 = gc[t*3+0], c1 = gc[t*3+1], c2 = gc[t*3+2];
        float s0 = gs[t*3+0], s1 = gs[t*3+1], s2 = gs[t*3+2];
        float h0s = __fmul_rn(s0, 0.5f), h1s = __fmul_rn(s1, 0.5f), h2s = __fmul_rn(s2, 0.5f);
        float l0 = __fsub_rn(c0, h0s), l1 = __fsub_rn(c1, h1s), l2 = __fsub_rn(c2, h2s);
        float h0 = __fadd_rn(c0, h0s), h1 = __fadd_rn(c1, h1s), h2 = __fadd_rn(c2, h2s);
        glo0[t]=l0; glo1[t]=l1; glo2[t]=l2; ghi0[t]=h0; ghi1[t]=h1; ghi2[t]=h2;
        gvol[t] = __fmul_rn(__fmul_rn(__fsub_rn(h0,l0), __fsub_rn(h1,l1)), __fsub_rn(h2,l2));
        glab[t] = d_labels[t];
    }
    __syncthreads();
    int p = blockIdx.x * blockDim.x + t;
    float c0 = pc[p*3+0], c1 = pc[p*3+1], c2 = pc[p*3+2];
    float s0 = ps[p*3+0], s1 = ps[p*3+1], s2 = ps[p*3+2];
    float h0s = __fmul_rn(s0, 0.5f), h1s = __fmul_rn(s1, 0.5f), h2s = __fmul_rn(s2, 0.5f);
    float pl0 = __fsub_rn(c0, h0s), pl1 = __fsub_rn(c1, h1s), pl2 = __fsub_rn(c2, h2s);
    float ph0 = __fadd_rn(c0, h0s), ph1 = __fadd_rn(c1, h1s), ph2 = __fadd_rn(c2, h2s);
    float vol1 = __fmul_rn(__fmul_rn(__fsub_rn(ph0,pl0), __fsub_rn(ph1,pl1)), __fsub_rn(ph2,pl2));
    const float* clsrow = cls + (size_t)p * N_CLS;

    #pragma unroll 4
    for (int g = 0; g < N_GT; g++) {
        float d0 = fmaxf(__fsub_rn(fminf(ph0, ghi0[g]), fmaxf(pl0, glo0[g])), 0.f);
        float d1 = fmaxf(__fsub_rn(fminf(ph1, ghi1[g]), fmaxf(pl1, glo1[g])), 0.f);
        float d2 = fmaxf(__fsub_rn(fminf(ph2, ghi2[g]), fmaxf(pl2, glo2[g])), 0.f);
        float ov = __fmul_rn(__fmul_rn(d0, d1), d2);
        float un = fmaxf(__fsub_rn(__fadd_rn(vol1, gvol[g]), ov), GEPS);
        float iou = __fdiv_rn(ov, un);
        float e0 = fmaxf(__fsub_rn(fmaxf(ph0, ghi0[g]), fminf(pl0, glo0[g])), 0.f);
        float e1 = fmaxf(__fsub_rn(fmaxf(ph1, ghi1[g]), fminf(pl1, glo1[g])), 0.f);
        float e2 = fmaxf(__fsub_rn(fmaxf(ph2, ghi2[g]), fminf(pl2, glo2[g])), 0.f);
        float enc = fmaxf(__fmul_rn(__fmul_rn(e0, e1), e2), GEPS);
        float gi = __fsub_rn(iou, __fdiv_rn(__fsub_rn(enc, un), enc));
        float cv = __ldg(clsrow + glab[g]);
        float sig = __fdiv_rn(1.0f, __fadd_rn(1.0f, expf(-cv)));
        d_giou[g][p] = gi;
        d_cost[g][p] = __fadd_rn(-sig, __fmul_rn(-2.0f, gi));
    }
}

// ------------------- selection: sample-threshold + sort (atomic-light) -------------------
// blocks 0..127: cost rows, exact 128 smallest (by value, idx tiebreak)
// blocks 128..255: giou rows, exact top-GC_NEED sorted desc + row max
__global__ void k_select() {
    __shared__ ull buf[SEL_CAP];     // 32KB (aliased as hist in rare fallback)
    __shared__ ull samp[512];        // 4KB
    __shared__ int   redi[256];
    __shared__ float redf[256];
    __shared__ int s_cnt, s_c;
    __shared__ unsigned s_T;

    int b = blockIdx.x, tid = threadIdx.x, nth = blockDim.x;  // nth = 256

    if (b < N_GT) {
        // ================= cost row =================
        int row = b;
        const float* crow = d_cost[row];
        for (int j = tid; j < 512; j += nth) {
            float v = crow[j * 128];
            samp[j] = ((ull)fkey(v) << 32) | (unsigned)(j * 128);
        }
        __syncthreads();
        bsort(samp, 512, tid, nth);

        const int slist[5] = {4, 16, 64, 255, 511};
        unsigned Tkey = 0;
        int c = 0;
        for (int si = 0; si < 5; si++) {
            Tkey = (unsigned)(samp[slist[si]] >> 32);
            int lc = 0;
            for (int j = tid; j < N_PRED; j += nth)
                lc += (fkey(crow[j]) <= Tkey) ? 1 : 0;
            redi[tid] = lc;
            __syncthreads();
            for (int off = nth >> 1; off > 0; off >>= 1) {
                if (tid < off) redi[tid] += redi[tid + off];
                __syncthreads();
            }
            c = redi[0];
            __syncthreads();
            if (c >= 128 && c <= SEL_CAP) break;
            if (c > SEL_CAP) {
                // extremely tie-heavy data: tighten to smallest sample and accept cap
                if (si == 0) { Tkey = (unsigned)(samp[0] >> 32); /* recount below via collect cap */ }
                break;
            }
        }
        if (tid == 0) { s_T = Tkey; s_cnt = 0; }
        __syncthreads();
        Tkey = s_T;
        for (int j = tid; j < N_PRED; j += nth) {
            unsigned k = fkey(crow[j]);
            if (k <= Tkey) {
                int slot = atomicAdd(&s_cnt, 1);
                if (slot < SEL_CAP) buf[slot] = ((ull)k << 32) | (unsigned)j;
            }
        }
        __syncthreads();
        int cc = s_cnt; if (cc > SEL_CAP) cc = SEL_CAP;
        int n2 = 256; while (n2 < cc) n2 <<= 1;
        for (int i = tid + cc; i < n2; i += nth) buf[i] = 0xFFFFFFFFFFFFFFFFull;
        __syncthreads();
        bsort(buf, n2, tid, nth);
        int keep = (cc < CAND_C) ? cc : CAND_C;
        for (int i = tid; i < keep; i += nth) {
            ull e = buf[i];
            int j = (int)(e & 0xFFFFFFFFull);
            d_ccand_idx[row][i] = j;
            d_ccand_val[row][i] = crow[j];
            atomicOr(&d_colbm[j >> 5], 1u << (j & 31));
        }
        if (tid == 0) d_ccand_cnt[row] = keep;
    } else {
        // ================= giou row =================
        int row = b - N_GT;
        const float* grow = d_giou[row];
        // pass 1: qualifying count + max
        float lmax = -1e30f; int lc = 0;
        for (int j = tid; j < N_PRED; j += nth) {
            float g = grow[j];
            lmax = fmaxf(lmax, g);
            lc += (g > IOU_THRES) ? 1 : 0;
        }
        redi[tid] = lc; redf[tid] = lmax;
        __syncthreads();
        for (int off = nth >> 1; off > 0; off >>= 1) {
            if (tid < off) { redi[tid] += redi[tid + off]; redf[tid] = fmaxf(redf[tid], redf[tid + off]); }
            __syncthreads();
        }
        int tot = redi[0];
        if (tid == 0) { d_maxg[row] = redf[0]; s_cnt = 0; s_c = 0; }
        __syncthreads();

        unsigned pfx22 = 0xFFFFFFFFu; int all = 1;
        if (tot > SEL_CAP) {
            // rare fallback: 2-level 2048-bin histogram over qualifiers only
            all = 0;
            unsigned* hist = (unsigned*)buf;
            // level 0: bits [31:21] of key = ~fkey(g)
            for (int i = tid; i < 2048; i += nth) hist[i] = 0;
            __syncthreads();
            for (int j = tid; j < N_PRED; j += nth) {
                float g = grow[j];
                if (g > IOU_THRES) atomicAdd(&hist[(~fkey(g)) >> 21], 1u);
            }
            __syncthreads();
            if (tid == 0) {
                unsigned need = GC_NEED, cum = 0; int bb = 0;
                for (; bb < 2047; bb++) { if (cum + hist[bb] >= need) break; cum += hist[bb]; }
                s_c = bb; s_cnt = (int)(need - cum);
            }
            __syncthreads();
            unsigned pfx11 = (unsigned)s_c; int need1 = s_cnt;
            __syncthreads();
            // level 1: bits [20:10] within pfx11
            for (int i = tid; i < 2048; i += nth) hist[i] = 0;
            __syncthreads();
            for (int j = tid; j < N_PRED; j += nth) {
                float g = grow[j];
                if (g > IOU_THRES) {
                    unsigned k = ~fkey(g);
                    if ((k >> 21) == pfx11) atomicAdd(&hist[(k >> 10) & 2047u], 1u);
                }
            }
            __syncthreads();
            if (tid == 0) {
                unsigned need = (unsigned)need1, cum = 0; int bb = 0;
                for (; bb < 2047; bb++) { if (cum + hist[bb] >= need) break; cum += hist[bb]; }
                s_c = (int)((pfx11 << 11) | (unsigned)bb);
                s_cnt = 0;
            }
            __syncthreads();
            pfx22 = (unsigned)s_c;
            __syncthreads();
        }
        // collect
        for (int j = tid; j < N_PRED; j += nth) {
            float g = grow[j];
            if (!(g > IOU_THRES)) continue;
            unsigned k = ~fkey(g);
            if (all || ((k >> 10) <= pfx22)) {
                int slot = atomicAdd(&s_cnt, 1);
                if (slot < SEL_CAP) buf[slot] = ((ull)k << 32) | (unsigned)j;
            }
        }
        __syncthreads();
        int cc = s_cnt; if (cc > SEL_CAP) cc = SEL_CAP;
        int n2 = 256; while (n2 < cc) n2 <<= 1;
        for (int i = tid + cc; i < n2; i += nth) buf[i] = 0xFFFFFFFFFFFFFFFFull;
        __syncthreads();
        bsort(buf, n2, tid, nth);   // key asc == giou desc, idx asc
        int cnt = (cc < GC_NEED) ? cc : GC_NEED;
        for (int i = tid; i < cnt; i += nth)
            d_gcand_idx[row][i] = (int)(buf[i] & 0xFFFFFFFFull);
        if (tid == 0) d_gcand_cnt[row] = cnt;
    }
}

// ------------------- stable argsort (ascending) of maxg -------------------
__global__ void k_order() {
    __shared__ float v[N_GT];
    int t = threadIdx.x;
    v[t] = d_maxg[t];
    __syncthreads();
    float mv = v[t]; int r = 0;
    for (int j = 0; j < N_GT; j++) {
        float o = v[j];
        if (o < mv || (o == mv && j < t)) r++;
    }
    d_order[r] = t;
}

// ------------------- compact column ids: popc scan over bitmap -------------------
__global__ void k_compact() {   // 1 block, 256 threads; 2048 words, 8 per thread
    __shared__ int tsum[256];
    int tid = threadIdx.x;
    int base = tid * 8;
    int cnts[8]; int s = 0;
    #pragma unroll
    for (int w = 0; w < 8; w++) { cnts[w] = __popc(d_colbm[base + w]); s += cnts[w]; }
    tsum[tid] = s;
    __syncthreads();
    for (int off = 1; off < 256; off <<= 1) {
        int v_ = 0;
        if (tid >= off) v_ = tsum[tid - off];
        __syncthreads();
        tsum[tid] += v_;
        __syncthreads();
    }
    int excl = tsum[tid] - s;
    #pragma unroll
    for (int w = 0; w < 8; w++) { d_cbase[base + w] = excl; excl += cnts[w]; }
    if (tid == 255) d_nK = tsum[255];
}

// ------------------- remap candidates to compact ids + reverse map -------------------
__global__ void k_remap() {
    int row = blockIdx.x;
    int cnt = d_ccand_cnt[row];
    for (int s = threadIdx.x; s < cnt; s += blockDim.x) {
        int j = d_ccand_idx[row][s];
        int w = j >> 5;
        int cid = d_cbase[w] + __popc(d_colbm[w] & ((1u << (j & 31)) - 1u));
        d_ccand_idx[row][s] = cid;
        d_rev[cid] = j;
    }
}

// ------------------- init global LSA state (fallback + v) ---------------
__global__ void k_initgl() {
    int i = blockIdx.x * blockDim.x + threadIdx.x;
    if (i < N_PRED) {
        d_v[i] = 0.0; d_stampA[i] = 0; d_stampSC[i] = 0; d_row4col[i] = -1;
    }
}

// ------------------- sparse JV LSA: greedy tight init + rare augmentations ------------
__global__ void k_lsa() {
    extern __shared__ unsigned char dsm[];
    double*   shS  = (double*)dsm;                         // [LSA_CAP] shortest
    uint16_t* shT  = (uint16_t*)(dsm + (size_t)LSA_CAP*8); // [LSA_CAP] touched list
    uint8_t*  shP  = dsm + (size_t)LSA_CAP*10;             // [LSA_CAP] path (row)
    uint8_t*  shR  = dsm + (size_t)LSA_CAP*11;             // [LSA_CAP] row4col (255=free)
    unsigned* shSC = (unsigned*)(dsm + (size_t)LSA_CAP*12);// [LSA_CAP/32] SC bitmap

    __shared__ double u[N_GT];
    __shared__ int SR[N_GT];
    __shared__ int c4r[N_GT];
    __shared__ int   pend[N_GT];
    __shared__ double rv[256];
    __shared__ int ri[256];
    __shared__ int s_nSR, s_row, s_sink, s_nT, s_npend;
    __shared__ double s_minval;

    int tid = threadIdx.x, nth = blockDim.x;  // 256
    int nK = d_nK;
    const double DINF = 1e300;

    if (nK <= LSA_CAP) {
        // ---- init smem state ----
        for (int i = tid; i < LSA_CAP; i += nth) shS[i] = DINF;
        for (int i = tid; i < LSA_CAP; i += nth) shR[i] = 0xFF;
        for (int i = tid; i < LSA_CAP/32; i += nth) shSC[i] = 0;
        for (int i = tid; i < N_GT; i += nth) c4r[i] = -1;
        __syncthreads();

        // ---- greedy tight assignment: candidate lists are sorted, slot 0 is row argmin ----
        if (tid == 0) {
            s_npend = 0;
            for (int i = 0; i < N_GT; i++) {
                u[i] = (double)d_ccand_val[i][0];
                int j = d_ccand_idx[i][0];
                if (j >= 0 && j < nK && shR[j] == 0xFF) {
                    shR[j] = (uint8_t)i; c4r[i] = j;
                } else {
                    pend[s_npend++] = i;
                }
            }
        }
        __syncthreads();
        int npend = s_npend;

        // ---- shortest augmenting path for each conflicted row ----
        for (int pi = 0; pi < npend; pi++) {
            int cur = pend[pi];
            if (tid == 0) { s_nSR = 0; s_row = cur; s_sink = -1; s_nT = 0; s_minval = 0.0; }
            __syncthreads();
            for (int step = 0; step < N_GT; step++) {
                int i = s_row;
                if (tid == 0) SR[s_nSR++] = i;
                double mv0 = s_minval, ui = u[i];
                int cnt = d_ccand_cnt[i];
                for (int s = tid; s < cnt; s += nth) {
                    int jc = d_ccand_idx[i][s];
                    if ((shSC[jc >> 5] >> (jc & 31)) & 1u) continue;
                    double r = ((mv0 + (double)d_ccand_val[i][s]) - ui) - d_v[jc];
                    double old = shS[jc];
                    if (r < old) {
                        if (old == DINF) { int t2 = atomicAdd(&s_nT, 1); shT[t2] = (uint16_t)jc; }
                        shS[jc] = r; shP[jc] = (uint8_t)i;
                    }
                }
                __syncthreads();
                double bv = DINF; int bj = 0x7fffffff;
                int nT = s_nT;
                for (int t2 = tid; t2 < nT; t2 += nth) {
                    int jc = shT[t2];
                    if ((shSC[jc >> 5] >> (jc & 31)) & 1u) continue;
                    double sv = shS[jc];
                    if (sv < bv || (sv == bv && jc < bj)) { bv = sv; bj = jc; }
                }
                rv[tid] = bv; ri[tid] = bj;
                __syncthreads();
                for (int off = nth >> 1; off > 0; off >>= 1) {
                    if (tid < off) {
                        double ov = rv[tid + off]; int oj = ri[tid + off];
                        if (ov < rv[tid] || (ov == rv[tid] && oj < ri[tid])) { rv[tid] = ov; ri[tid] = oj; }
                    }
                    __syncthreads();
                }
                if (tid == 0) {
                    int j = ri[0];
                    if (j >= 0 && j < nK) {
                        s_minval = rv[0];
                        shSC[j >> 5] |= (1u << (j & 31));
                        int r4 = shR[j];
                        if (r4 == 0xFF) s_sink = j; else s_row = r4;
                    } else s_sink = -2;
                }
                __syncthreads();
                if (s_sink != -1) break;
            }
            if (s_sink >= 0) {
                if (tid == 0) {
                    u[cur] += s_minval;
                    for (int k = 1; k < s_nSR; k++) {
                        int i2 = SR[k];
                        u[i2] += s_minval - shS[c4r[i2]];
                    }
                }
                int nT = s_nT; double mv = s_minval;
                for (int t2 = tid; t2 < nT; t2 += nth) {
                    int jc = shT[t2];
                    if ((shSC[jc >> 5] >> (jc & 31)) & 1u) d_v[jc] -= mv - shS[jc];
                }
                __syncthreads();
                if (tid == 0) {
                    int j = s_sink;
                    for (int it = 0; it <= N_GT && j >= 0; it++) {
                        int i2 = shP[j];
                        shR[j] = (uint8_t)i2;
                        int tmp = c4r[i2];
                        c4r[i2] = j;
                        j = tmp;
                        if (i2 == cur) break;
                    }
                }
            }
            __syncthreads();
            int nT = s_nT;
            for (int t2 = tid; t2 < nT; t2 += nth) shS[shT[t2]] = DINF;
            for (int i = tid; i < (nK + 31) / 32; i += nth) shSC[i] = 0;
            __syncthreads();
        }
        if (tid < N_GT) d_col4row[tid] = d_rev[c4r[tid]];
    } else {
        // =============== fallback path: global state (validated logic; unreachable now) ====
        for (int i = tid; i < N_GT; i += nth) { u[i] = 0.0; c4r[i] = -1; }
        __syncthreads();
        for (int cur = 0; cur < N_GT; cur++) {
            int stamp = cur + 1;
            if (tid == 0) { s_nSR = 0; s_row = cur; s_sink = -1; s_nT = 0; s_minval = 0.0; }
            __syncthreads();
            for (int step = 0; step < N_GT; step++) {
                int i = s_row;
                if (tid == 0) SR[s_nSR++] = i;
                double mv0 = s_minval, ui = u[i];
                int cnt = d_ccand_cnt[i];
                for (int s = tid; s < cnt; s += nth) {
                    int jc = d_ccand_idx[i][s];
                    if (d_stampSC[jc] == stamp) continue;
                    double r = ((mv0 + (double)d_ccand_val[i][s]) - ui) - d_v[jc];
                    if (d_stampA[jc] != stamp) {
                        d_stampA[jc] = stamp;
                        d_shortest[jc] = r; d_path[jc] = i;
                        int t2 = atomicAdd(&s_nT, 1);
                        d_Tg[t2] = jc;
                    } else if (r < d_shortest[jc]) {
                        d_shortest[jc] = r; d_path[jc] = i;
                    }
                }
                __syncthreads();
                double bv = DINF; int bj = 0x7fffffff;
                int nT = s_nT;
                for (int t2 = tid; t2 < nT; t2 += nth) {
                    int jc = d_Tg[t2];
                    if (d_stampSC[jc] == stamp) continue;
                    double sv = d_shortest[jc];
                    if (sv < bv || (sv == bv && jc < bj)) { bv = sv; bj = jc; }
                }
                rv[tid] = bv; ri[tid] = bj;
                __syncthreads();
                for (int off = nth >> 1; off > 0; off >>= 1) {
                    if (tid < off) {
                        double ov = rv[tid + off]; int oj = ri[tid + off];
                        if (ov < rv[tid] || (ov == rv[tid] && oj < ri[tid])) { rv[tid] = ov; ri[tid] = oj; }
                    }
                    __syncthreads();
                }
                if (tid == 0) {
                    int j = ri[0];
                    if (j >= 0 && j < N_PRED) {
                        s_minval = rv[0];
                        d_stampSC[j] = stamp;
                        if (d_row4col[j] < 0) s_sink = j; else s_row = d_row4col[j];
                    } else s_sink = -2;
                }
                __syncthreads();
                if (s_sink != -1) break;
            }
            if (s_sink >= 0) {
                if (tid == 0) {
                    u[cur] += s_minval;
                    for (int k = 1; k < s_nSR; k++) {
                        int i2 = SR[k];
                        u[i2] += s_minval - d_shortest[c4r[i2]];
                    }
                }
                int nT = s_nT; double mv = s_minval;
                for (int t2 = tid; t2 < nT; t2 += nth) {
                    int jc = d_Tg[t2];
                    if (d_stampSC[jc] == stamp) d_v[jc] -= mv - d_shortest[jc];
                }
                __syncthreads();
                if (tid == 0) {
                    int j = s_sink;
                    for (int it = 0; it <= N_GT && j >= 0; it++) {
                        int i2 = d_path[j];
                        d_row4col[j] = i2;
                        int tmp = c4r[i2];
                        c4r[i2] = j;
                        j = tmp;
                        if (i2 == cur) break;
                    }
                }
            }
            __syncthreads();
        }
        if (tid < N_GT) d_col4row[tid] = d_rev[c4r[tid]];
    }
}

// ------------------- dynamic assignment + float32 output -------------------
__global__ void k_dyn(float* __restrict__ out) {
    __shared__ unsigned used[NBMW];   // 8KB
    __shared__ int res_p[1408];
    __shared__ int res_g[1408];
    __shared__ int pref[N_GT][32];    // 16KB: first 32 candidates per gt
    __shared__ int cnts[N_GT], ordv[N_GT];
    int tid = threadIdx.x;
    for (int i = tid; i < NBMW; i += blockDim.x) used[i] = 0;
    if (tid < N_GT) { cnts[tid] = d_gcand_cnt[tid]; ordv[tid] = d_order[tid]; }
    __syncthreads();
    for (int i = tid; i < N_GT * 32; i += blockDim.x) {
        int g = i >> 5, s = i & 31;
        pref[g][s] = (s < cnts[g]) ? d_gcand_idx[g][s] : -1;
    }
    if (tid < N_GT) {
        int p = d_col4row[tid];
        if (p >= 0 && p < N_PRED) atomicOr(&used[p >> 5], 1u << (p & 31));
        res_p[tid] = p;
        res_g[tid] = tid;
    }
    __syncthreads();
    if (tid < 32) {
        int lane = tid;
        for (int t = 0; t < N_GT; t++) {
            int g = ordv[t];
            int cnt = cnts[g];
            int picked = 0;
            for (int base = 0; base < cnt && picked < MAX_DYN; base += 32) {
                int idx = -1;
                if (base + lane < cnt)
                    idx = (base == 0) ? pref[g][lane] : d_gcand_idx[g][base + lane];
                bool elig = (idx >= 0) && (idx < N_PRED) && !((used[idx >> 5] >> (idx & 31)) & 1u);
                unsigned m = __ballot_sync(0xffffffffu, elig);
                int K = MAX_DYN - picked;
                int pre = __popc(m & ((1u << lane) - 1u));
                if (elig && pre < K) {
                    atomicOr(&used[idx >> 5], 1u << (idx & 31));
                    res_p[128 + t * MAX_DYN + picked + pre] = idx;
                    res_g[128 + t * MAX_DYN + picked + pre] = g;
                }
                int got = __popc(m); if (got > K) got = K;
                picked += got;
                __syncwarp();
            }
            if (lane >= picked && lane < MAX_DYN) {
                res_p[128 + t * MAX_DYN + lane] = -1;
                res_g[128 + t * MAX_DYN + lane] = -1;
            }
            __syncwarp();
        }
    }
    __syncthreads();
    for (int i = tid; i < 1408; i += blockDim.x) {
        out[i]        = (float)res_p[i];
        out[1408 + i] = (float)res_g[i];
    }
}

// ------------------- launch (inputs resolved by element count) -------------------
extern "C" void kernel_launch(void* const* d_in, const int* in_sizes, int n_in,
                              void* d_out, int out_size) {
    const float* all_centers = 0;
    const float* all_sizes   = 0;
    const float* all_cls     = 0;
    const float* gt_centers  = 0;
    const float* gt_sizes    = 0;
    const void*  gt_labels   = 0;
    int seen196 = 0, seen384 = 0;
    for (int i = 0; i < n_in; i++) {
        long long s = in_sizes[i];
        if (s == (long long)N_PRED * N_CLS) {
            all_cls = (const float*)d_in[i];
        } else if (s == (long long)N_PRED * 3) {
            if (seen196++ == 0) all_centers = (const float*)d_in[i];
            else                all_sizes   = (const float*)d_in[i];
        } else if (s == (long long)N_GT * 3) {
            if (seen384++ == 0) gt_centers = (const float*)d_in[i];
            else                gt_sizes   = (const float*)d_in[i];
        } else if (s == (long long)N_GT) {
            gt_labels = d_in[i];
        }
    }

    cudaFuncSetAttribute(k_lsa, cudaFuncAttributeMaxDynamicSharedMemorySize, LSA_DYN_BYTES);

    k_labels<<<1, 128>>>(gt_labels);
    k_cost<<<N_PRED / 128, 128>>>(all_centers, all_sizes, all_cls, gt_centers, gt_sizes);
    k_select<<<2 * N_GT, 256>>>();
    k_order<<<1, N_GT>>>();
    k_compact<<<1, 256>>>();
    k_remap<<<N_GT, 128>>>();
    k_initgl<<<N_PRED / 256, 256>>>();
    k_lsa<<<1, 256, LSA_DYN_BYTES>>>();
    k_dyn<<<1, 256>>>((float*)d_out);
}

// round 8
// speedup vs baseline: 4.3589x; 1.1199x over previous
#include <cuda_runtime.h>
#include <math.h>
#include <stdint.h>

#define N_PRED 65536
#define N_GT   128
#define N_CLS  256
#define MAX_DYN 10
#define GEPS   1e-6f
#define IOU_THRES 0.25f
#define CAND_C 128      // per-row LSA candidates: exactly the 128 smallest
#define SEL_CAP 4096    // collection buffer cap (smem)
#define GC_NEED 1408    // per-gt dynamic candidate depth (10 + 128 + 10*127)
#define NBMW   (N_PRED/32)   // 2048 bitmap words
#define LSA_CAP 18176        // smem LSA capacity; union <= 128*128 = 16384 < LSA_CAP
#define LSA_DYN_BYTES (LSA_CAP*12 + LSA_CAP/8)  // 220384

typedef unsigned long long ull;

// ------------------- scratch (device globals; no runtime allocation) -------------------
__device__ float  d_cost[N_GT][N_PRED];   // 32MB  cost_T[g][p]
__device__ float  d_giou[N_GT][N_PRED];   // 32MB  giou_T[g][p]
__device__ float  d_maxg[N_GT];
__device__ int    d_labels[N_GT];

__device__ int    d_ccand_idx[N_GT][CAND_C];  // sorted (cost,idx) asc; compact ids after k_lsa remap
__device__ float  d_ccand_val[N_GT][CAND_C];
__device__ int    d_ccand_cnt[N_GT];

__device__ int    d_gcand_idx[N_GT][GC_NEED];
__device__ int    d_gcand_cnt[N_GT];

__device__ unsigned d_colbm[NBMW];
__device__ int    d_rev[N_PRED];          // compact id -> orig col
__device__ double d_v[N_PRED];            // column duals (compact-indexed), zeroed in k_lsa
__device__ int    d_col4row[N_GT];        // final ORIG pred idx per gt

// monotonic ascending key for float
__device__ __forceinline__ unsigned fkey(float f) {
    unsigned u = __float_as_uint(f);
    return (u & 0x80000000u) ? ~u : (u | 0x80000000u);
}

// block bitonic sort, ascending, n = power of two >= blockDim
__device__ __forceinline__ void bsort(ull* a, int n, int tid, int nth) {
    for (int k = 2; k <= n; k <<= 1) {
        for (int j = k >> 1; j > 0; j >>= 1) {
            for (int i = tid; i < n; i += nth) {
                int ixj = i ^ j;
                if (ixj > i) {
                    bool up = ((i & k) == 0);
                    ull x = a[i], y = a[ixj];
                    if ((x > y) == up) { a[i] = y; a[ixj] = x; }
                }
            }
            __syncthreads();
        }
    }
}

// ------------------- labels decode + bitmap zero -------------------
__global__ void k_labels(const void* lab) {
    __shared__ int is32;
    if (threadIdx.x == 0) {
        const ull* p = (const ull*)lab;
        int f = 0;
        for (int i = 0; i < 64; i++) { if (p[i] >> 32) { f = 1; break; } }
        is32 = f;
    }
    __syncthreads();
    int t = threadIdx.x;
    if (t < N_GT) {
        long long v;
        if (is32) v = (long long)((const int*)lab)[t];
        else      v = ((const long long*)lab)[t];
        int iv = (int)v;
        if (iv < 0) iv = 0;
        if (iv >= N_CLS) iv = N_CLS - 1;
        d_labels[t] = iv;
    }
    for (int i = t; i < NBMW; i += blockDim.x) d_colbm[i] = 0u;
}

// ------------------- cost + giou matrices (validated fp32; 4-way g-split) -------------
__global__ void k_cost(const float* __restrict__ pc, const float* __restrict__ ps,
                       const float* __restrict__ cls,
                       const float* __restrict__ gc, const float* __restrict__ gs) {
    __shared__ float glo0[N_GT], glo1[N_GT], glo2[N_GT];
    __shared__ float ghi0[N_GT], ghi1[N_GT], ghi2[N_GT];
    __shared__ float gvol[N_GT];
    __shared__ int   glab[N_GT];
    int tid = threadIdx.x;  // blockDim = 512
    if (tid < N_GT) {
        int t = tid;
        float c0 = gc[t*3+0], c1 = gc[t*3+1], c2 = gc[t*3+2];
        float s0 = gs[t*3+0], s1 = gs[t*3+1], s2 = gs[t*3+2];
        float h0s = __fmul_rn(s0, 0.5f), h1s = __fmul_rn(s1, 0.5f), h2s = __fmul_rn(s2, 0.5f);
        float l0 = __fsub_rn(c0, h0s), l1 = __fsub_rn(c1, h1s), l2 = __fsub_rn(c2, h2s);
        float h0 = __fadd_rn(c0, h0s), h1 = __fadd_rn(c1, h1s), h2 = __fadd_rn(c2, h2s);
        glo0[t]=l0; glo1[t]=l1; glo2[t]=l2; ghi0[t]=h0; ghi1[t]=h1; ghi2[t]=h2;
        gvol[t] = __fmul_rn(__fmul_rn(__fsub_rn(h0,l0), __fsub_rn(h1,l1)), __fsub_rn(h2,l2));
        glab[t] = d_labels[t];
    }
    __syncthreads();
    int p = blockIdx.x * 128 + (tid & 127);
    int gbase = (tid >> 7) * 32;          // 4 quarters of the g-loop
    float c0 = pc[p*3+0], c1 = pc[p*3+1], c2 = pc[p*3+2];
    float s0 = ps[p*3+0], s1 = ps[p*3+1], s2 = ps[p*3+2];
    float h0s = __fmul_rn(s0, 0.5f), h1s = __fmul_rn(s1, 0.5f), h2s = __fmul_rn(s2, 0.5f);
    float pl0 = __fsub_rn(c0, h0s), pl1 = __fsub_rn(c1, h1s), pl2 = __fsub_rn(c2, h2s);
    float ph0 = __fadd_rn(c0, h0s), ph1 = __fadd_rn(c1, h1s), ph2 = __fadd_rn(c2, h2s);
    float vol1 = __fmul_rn(__fmul_rn(__fsub_rn(ph0,pl0), __fsub_rn(ph1,pl1)), __fsub_rn(ph2,pl2));
    const float* clsrow = cls + (size_t)p * N_CLS;

    #pragma unroll 4
    for (int gi_ = 0; gi_ < 32; gi_++) {
        int g = gbase + gi_;
        float d0 = fmaxf(__fsub_rn(fminf(ph0, ghi0[g]), fmaxf(pl0, glo0[g])), 0.f);
        float d1 = fmaxf(__fsub_rn(fminf(ph1, ghi1[g]), fmaxf(pl1, glo1[g])), 0.f);
        float d2 = fmaxf(__fsub_rn(fminf(ph2, ghi2[g]), fmaxf(pl2, glo2[g])), 0.f);
        float ov = __fmul_rn(__fmul_rn(d0, d1), d2);
        float un = fmaxf(__fsub_rn(__fadd_rn(vol1, gvol[g]), ov), GEPS);
        float iou = __fdiv_rn(ov, un);
        float e0 = fmaxf(__fsub_rn(fmaxf(ph0, ghi0[g]), fminf(pl0, glo0[g])), 0.f);
        float e1 = fmaxf(__fsub_rn(fmaxf(ph1, ghi1[g]), fminf(pl1, glo1[g])), 0.f);
        float e2 = fmaxf(__fsub_rn(fmaxf(ph2, ghi2[g]), fminf(pl2, glo2[g])), 0.f);
        float enc = fmaxf(__fmul_rn(__fmul_rn(e0, e1), e2), GEPS);
        float gg = __fsub_rn(iou, __fdiv_rn(__fsub_rn(enc, un), enc));
        float cv = __ldg(clsrow + glab[g]);
        float sig = __fdiv_rn(1.0f, __fadd_rn(1.0f, expf(-cv)));
        d_giou[g][p] = gg;
        d_cost[g][p] = __fadd_rn(-sig, __fmul_rn(-2.0f, gg));
    }
}

// ------------------- selection: single-pass sample-threshold + sort -------------------
// blocks 0..127: cost rows (exact 128 smallest); 128..255: giou rows (top-GC_NEED + max)
__global__ void k_select() {
    __shared__ ull buf[SEL_CAP];     // 32KB (aliased as hist in rare fallbacks)
    __shared__ ull samp[512];
    __shared__ int   redi[512];
    __shared__ float redf[512];
    __shared__ int s_cnt, s_c;

    int b = blockIdx.x, tid = threadIdx.x, nth = blockDim.x;  // nth = 512
    unsigned* hist = (unsigned*)buf;   // 2048-bin fallback histogram

    if (b < N_GT) {
        // ================= cost row =================
        int row = b;
        const float* crow = d_cost[row];
        if (tid < 512) {
            float v = crow[tid * 128];
            samp[tid] = ((ull)fkey(v) << 32) | (unsigned)(tid * 128);
        }
        __syncthreads();
        bsort(samp, 512, tid, nth);

        const int slist[5] = {4, 16, 64, 255, 511};
        int si = 0, cc = 0, truecnt = 0;
        while (true) {
            if (tid == 0) s_cnt = 0;
            __syncthreads();
            unsigned Tkey = (unsigned)(samp[slist[si]] >> 32);
            for (int j = tid; j < N_PRED; j += nth) {
                unsigned k = fkey(crow[j]);
                if (k <= Tkey) {
                    int slot = atomicAdd(&s_cnt, 1);
                    if (slot < SEL_CAP) buf[slot] = ((ull)k << 32) | (unsigned)j;
                }
            }
            __syncthreads();
            truecnt = s_cnt;
            cc = (truecnt < SEL_CAP) ? truecnt : SEL_CAP;
            if (truecnt >= CAND_C && truecnt <= SEL_CAP) break;
            if (truecnt > SEL_CAP) {
                // rare: tie-heavy. exact 2-level 2048-bin histogram for the 128th key.
                for (int i = tid; i < 2048; i += nth) hist[i] = 0;
                __syncthreads();
                for (int j = tid; j < N_PRED; j += nth)
                    atomicAdd(&hist[fkey(crow[j]) >> 21], 1u);
                __syncthreads();
                if (tid == 0) {
                    unsigned need = CAND_C, cum = 0; int bb = 0;
                    for (; bb < 2047; bb++) { if (cum + hist[bb] >= need) break; cum += hist[bb]; }
                    s_c = bb; s_cnt = (int)(need - cum);
                }
                __syncthreads();
                unsigned pfx11 = (unsigned)s_c; int need1 = s_cnt;
                __syncthreads();
                for (int i = tid; i < 2048; i += nth) hist[i] = 0;
                __syncthreads();
                for (int j = tid; j < N_PRED; j += nth) {
                    unsigned k = fkey(crow[j]);
                    if ((k >> 21) == pfx11) atomicAdd(&hist[(k >> 10) & 2047u], 1u);
                }
                __syncthreads();
                if (tid == 0) {
                    unsigned need = (unsigned)need1, cum = 0; int bb = 0;
                    for (; bb < 2047; bb++) { if (cum + hist[bb] >= need) break; cum += hist[bb]; }
                    s_c = (int)((pfx11 << 11) | (unsigned)bb);
                    s_cnt = 0;
                }
                __syncthreads();
                unsigned pfx22 = (unsigned)s_c;
                __syncthreads();
                for (int j = tid; j < N_PRED; j += nth) {
                    unsigned k = fkey(crow[j]);
                    if ((k >> 10) <= pfx22) {
                        int slot = atomicAdd(&s_cnt, 1);
                        if (slot < SEL_CAP) buf[slot] = ((ull)k << 32) | (unsigned)j;
                    }
                }
                __syncthreads();
                truecnt = s_cnt;
                cc = (truecnt < SEL_CAP) ? truecnt : SEL_CAP;
                break;
            }
            si++;
            if (si >= 5) break;   // degenerate: take what we have
            __syncthreads();
        }
        int n2 = 512; while (n2 < cc) n2 <<= 1;
        for (int i = tid + cc; i < n2; i += nth) buf[i] = 0xFFFFFFFFFFFFFFFFull;
        __syncthreads();
        bsort(buf, n2, tid, nth);
        int keep = (cc < CAND_C) ? cc : CAND_C;
        for (int i = tid; i < keep; i += nth) {
            ull e = buf[i];
            int j = (int)(e & 0xFFFFFFFFull);
            d_ccand_idx[row][i] = j;
            d_ccand_val[row][i] = crow[j];
            atomicOr(&d_colbm[j >> 5], 1u << (j & 31));
        }
        if (tid == 0) d_ccand_cnt[row] = keep;
    } else {
        // ================= giou row: fused max + collect =================
        int row = b - N_GT;
        const float* grow = d_giou[row];
        if (tid == 0) s_cnt = 0;
        __syncthreads();
        float lmax = -1e30f;
        for (int j = tid; j < N_PRED; j += nth) {
            float g = grow[j];
            lmax = fmaxf(lmax, g);
            if (g > IOU_THRES) {
                int slot = atomicAdd(&s_cnt, 1);
                if (slot < SEL_CAP) buf[slot] = ((ull)(~fkey(g)) << 32) | (unsigned)j;
            }
        }
        redf[tid] = lmax;
        __syncthreads();
        for (int off = nth >> 1; off > 0; off >>= 1) {
            if (tid < off) redf[tid] = fmaxf(redf[tid], redf[tid + off]);
            __syncthreads();
        }
        if (tid == 0) d_maxg[row] = redf[0];
        int tot = s_cnt;
        __syncthreads();
        if (tot > SEL_CAP) {
            // rare overflow: 2-level histogram over qualifiers, then bounded re-collect
            for (int i = tid; i < 2048; i += nth) hist[i] = 0;
            __syncthreads();
            for (int j = tid; j < N_PRED; j += nth) {
                float g = grow[j];
                if (g > IOU_THRES) atomicAdd(&hist[(~fkey(g)) >> 21], 1u);
            }
            __syncthreads();
            if (tid == 0) {
                unsigned need = GC_NEED, cum = 0; int bb = 0;
                for (; bb < 2047; bb++) { if (cum + hist[bb] >= need) break; cum += hist[bb]; }
                s_c = bb; s_cnt = (int)(need - cum);
            }
            __syncthreads();
            unsigned pfx11 = (unsigned)s_c; int need1 = s_cnt;
            __syncthreads();
            for (int i = tid; i < 2048; i += nth) hist[i] = 0;
            __syncthreads();
            for (int j = tid; j < N_PRED; j += nth) {
                float g = grow[j];
                if (g > IOU_THRES) {
                    unsigned k = ~fkey(g);
                    if ((k >> 21) == pfx11) atomicAdd(&hist[(k >> 10) & 2047u], 1u);
                }
            }
            __syncthreads();
            if (tid == 0) {
                unsigned need = (unsigned)need1, cum = 0; int bb = 0;
                for (; bb < 2047; bb++) { if (cum + hist[bb] >= need) break; cum += hist[bb]; }
                s_c = (int)((pfx11 << 11) | (unsigned)bb);
                s_cnt = 0;
            }
            __syncthreads();
            unsigned pfx22 = (unsigned)s_c;
            __syncthreads();
            for (int j = tid; j < N_PRED; j += nth) {
                float g = grow[j];
                if (!(g > IOU_THRES)) continue;
                unsigned k = ~fkey(g);
                if ((k >> 10) <= pfx22) {
                    int slot = atomicAdd(&s_cnt, 1);
                    if (slot < SEL_CAP) buf[slot] = ((ull)k << 32) | (unsigned)j;
                }
            }
            __syncthreads();
            tot = s_cnt;
        }
        int cc = (tot < SEL_CAP) ? tot : SEL_CAP;
        int n2 = 512; while (n2 < cc) n2 <<= 1;
        for (int i = tid + cc; i < n2; i += nth) buf[i] = 0xFFFFFFFFFFFFFFFFull;
        __syncthreads();
        bsort(buf, n2, tid, nth);   // key asc == giou desc, idx asc
        int cnt = (cc < GC_NEED) ? cc : GC_NEED;
        for (int i = tid; i < cnt; i += nth)
            d_gcand_idx[row][i] = (int)(buf[i] & 0xFFFFFFFFull);
        if (tid == 0) d_gcand_cnt[row] = cnt;
    }
}

// ------------------- LSA: compact + remap + greedy tight + rare augmentations ---------
__global__ void k_lsa() {
    extern __shared__ unsigned char dsm[];
    double*   shS  = (double*)dsm;                         // [LSA_CAP] shortest
    uint16_t* shT  = (uint16_t*)(dsm + (size_t)LSA_CAP*8); // [LSA_CAP] touched list
    uint8_t*  shP  = dsm + (size_t)LSA_CAP*10;             // [LSA_CAP] path (row)
    uint8_t*  shR  = dsm + (size_t)LSA_CAP*11;             // [LSA_CAP] row4col (255=free)
    unsigned* shSC = (unsigned*)(dsm + (size_t)LSA_CAP*12);// [LSA_CAP/32] SC bitmap
    int*      cbase = (int*)shT;                            // alias: dead before augment

    __shared__ double u[N_GT];
    __shared__ int SR[N_GT];
    __shared__ int c4r[N_GT];
    __shared__ int pend[N_GT];
    __shared__ double rv[256];
    __shared__ int ri[256];
    __shared__ int tsum[256];
    __shared__ int s_nSR, s_row, s_sink, s_nT, s_npend;
    __shared__ double s_minval;

    int tid = threadIdx.x, nth = blockDim.x;  // 256
    const double DINF = 1e300;

    // ---- compact scan of column bitmap (2048 words, 8 per thread) ----
    int wbase = tid * 8;
    int cnts[8]; int ssum = 0;
    #pragma unroll
    for (int w = 0; w < 8; w++) { cnts[w] = __popc(d_colbm[wbase + w]); ssum += cnts[w]; }
    tsum[tid] = ssum;
    __syncthreads();
    for (int off = 1; off < 256; off <<= 1) {
        int v_ = 0;
        if (tid >= off) v_ = tsum[tid - off];
        __syncthreads();
        tsum[tid] += v_;
        __syncthreads();
    }
    int excl = tsum[tid] - ssum;
    #pragma unroll
    for (int w = 0; w < 8; w++) { cbase[wbase + w] = excl; excl += cnts[w]; }
    __syncthreads();
    int nK = tsum[255];
    if (nK > LSA_CAP) nK = LSA_CAP;   // impossible (union <= 16384), safety only

    // ---- remap candidates to compact ids + build reverse map; zero duals ----
    for (int x = tid; x < N_GT * CAND_C; x += nth) {
        int row = x >> 7, s = x & 127;
        if (s < d_ccand_cnt[row]) {
            int j = d_ccand_idx[row][s];
            int w = j >> 5;
            int cid = cbase[w] + __popc(d_colbm[w] & ((1u << (j & 31)) - 1u));
            d_ccand_idx[row][s] = cid;
            d_rev[cid] = j;
        }
    }
    for (int i = tid; i < nK; i += nth) d_v[i] = 0.0;
    __syncthreads();   // cbase dead after this point; shT free for touched-list

    // ---- init smem LSA state ----
    for (int i = tid; i < nK; i += nth) shS[i] = DINF;
    for (int i = tid; i < nK; i += nth) shR[i] = 0xFF;
    for (int i = tid; i < (nK + 31) / 32; i += nth) shSC[i] = 0;
    for (int i = tid; i < N_GT; i += nth) c4r[i] = -1;
    __syncthreads();

    // ---- greedy tight assignment (lists sorted: slot 0 = row argmin) ----
    if (tid == 0) {
        s_npend = 0;
        for (int i = 0; i < N_GT; i++) {
            int cnt = d_ccand_cnt[i];
            if (cnt > 0) {
                u[i] = (double)d_ccand_val[i][0];
                int j = d_ccand_idx[i][0];
                if (j >= 0 && j < nK && shR[j] == 0xFF) {
                    shR[j] = (uint8_t)i; c4r[i] = j;
                    continue;
                }
            } else u[i] = 0.0;
            pend[s_npend++] = i;
        }
    }
    __syncthreads();
    int npend = s_npend;

    // ---- shortest augmenting path per conflicted row ----
    for (int pi = 0; pi < npend; pi++) {
        int cur = pend[pi];
        if (tid == 0) { s_nSR = 0; s_row = cur; s_sink = -1; s_nT = 0; s_minval = 0.0; }
        __syncthreads();
        for (int step = 0; step < N_GT; step++) {
            int i = s_row;
            if (tid == 0) SR[s_nSR++] = i;
            double mv0 = s_minval, ui = u[i];
            int cnt = d_ccand_cnt[i];
            for (int s = tid; s < cnt; s += nth) {
                int jc = d_ccand_idx[i][s];
                if ((shSC[jc >> 5] >> (jc & 31)) & 1u) continue;
                double r = ((mv0 + (double)d_ccand_val[i][s]) - ui) - d_v[jc];
                double old = shS[jc];
                if (r < old) {
                    if (old == DINF) { int t2 = atomicAdd(&s_nT, 1); shT[t2] = (uint16_t)jc; }
                    shS[jc] = r; shP[jc] = (uint8_t)i;
                }
            }
            __syncthreads();
            double bv = DINF; int bj = 0x7fffffff;
            int nT = s_nT;
            for (int t2 = tid; t2 < nT; t2 += nth) {
                int jc = shT[t2];
                if ((shSC[jc >> 5] >> (jc & 31)) & 1u) continue;
                double sv = shS[jc];
                if (sv < bv || (sv == bv && jc < bj)) { bv = sv; bj = jc; }
            }
            rv[tid] = bv; ri[tid] = bj;
            __syncthreads();
            for (int off = nth >> 1; off > 0; off >>= 1) {
                if (tid < off) {
                    double ov = rv[tid + off]; int oj = ri[tid + off];
                    if (ov < rv[tid] || (ov == rv[tid] && oj < ri[tid])) { rv[tid] = ov; ri[tid] = oj; }
                }
                __syncthreads();
            }
            if (tid == 0) {
                int j = ri[0];
                if (j >= 0 && j < nK) {
                    s_minval = rv[0];
                    shSC[j >> 5] |= (1u << (j & 31));
                    int r4 = shR[j];
                    if (r4 == 0xFF) s_sink = j; else s_row = r4;
                } else s_sink = -2;
            }
            __syncthreads();
            if (s_sink != -1) break;
        }
        if (s_sink >= 0) {
            if (tid == 0) {
                u[cur] += s_minval;
                for (int k = 1; k < s_nSR; k++) {
                    int i2 = SR[k];
                    u[i2] += s_minval - shS[c4r[i2]];
                }
            }
            int nT = s_nT; double mv = s_minval;
            for (int t2 = tid; t2 < nT; t2 += nth) {
                int jc = shT[t2];
                if ((shSC[jc >> 5] >> (jc & 31)) & 1u) d_v[jc] -= mv - shS[jc];
            }
            __syncthreads();
            if (tid == 0) {
                int j = s_sink;
                for (int it = 0; it <= N_GT && j >= 0; it++) {
                    int i2 = shP[j];
                    shR[j] = (uint8_t)i2;
                    int tmp = c4r[i2];
                    c4r[i2] = j;
                    j = tmp;
                    if (i2 == cur) break;
                }
            }
        }
        __syncthreads();
        int nT = s_nT;
        for (int t2 = tid; t2 < nT; t2 += nth) shS[shT[t2]] = DINF;
        for (int i = tid; i < (nK + 31) / 32; i += nth) shSC[i] = 0;
        __syncthreads();
    }
    if (tid < N_GT) d_col4row[tid] = (c4r[tid] >= 0) ? d_rev[c4r[tid]] : -1;
}

// ------------------- dynamic assignment (incl. order) + float32 output ----------------
__global__ void k_dyn(float* __restrict__ out) {
    __shared__ unsigned used[NBMW];   // 8KB
    __shared__ int res_p[1408];
    __shared__ int res_g[1408];
    __shared__ int pref[N_GT][32];    // 16KB: first 32 candidates per gt
    __shared__ int cnts[N_GT], ordv[N_GT];
    __shared__ float mg[N_GT];
    int tid = threadIdx.x;
    for (int i = tid; i < NBMW; i += blockDim.x) used[i] = 0;
    if (tid < N_GT) { cnts[tid] = d_gcand_cnt[tid]; mg[tid] = d_maxg[tid]; }
    __syncthreads();
    // stable ascending argsort of maxg (rank per thread)
    if (tid < N_GT) {
        float mv = mg[tid]; int r = 0;
        for (int j = 0; j < N_GT; j++) {
            float o = mg[j];
            if (o < mv || (o == mv && j < tid)) r++;
        }
        ordv[r] = tid;
    }
    for (int i = tid; i < N_GT * 32; i += blockDim.x) {
        int g = i >> 5, s = i & 31;
        pref[g][s] = (s < cnts[g]) ? d_gcand_idx[g][s] : -1;
    }
    if (tid < N_GT) {
        int p = d_col4row[tid];
        if (p >= 0 && p < N_PRED) atomicOr(&used[p >> 5], 1u << (p & 31));
        res_p[tid] = p;
        res_g[tid] = tid;
    }
    __syncthreads();
    if (tid < 32) {
        int lane = tid;
        for (int t = 0; t < N_GT; t++) {
            int g = ordv[t];
            int cnt = cnts[g];
            int picked = 0;
            for (int base = 0; base < cnt && picked < MAX_DYN; base += 32) {
                int idx = -1;
                if (base + lane < cnt)
                    idx = (base == 0) ? pref[g][lane] : d_gcand_idx[g][base + lane];
                bool elig = (idx >= 0) && (idx < N_PRED) && !((used[idx >> 5] >> (idx & 31)) & 1u);
                unsigned m = __ballot_sync(0xffffffffu, elig);
                int K = MAX_DYN - picked;
                int pre = __popc(m & ((1u << lane) - 1u));
                if (elig && pre < K) {
                    atomicOr(&used[idx >> 5], 1u << (idx & 31));
                    res_p[128 + t * MAX_DYN + picked + pre] = idx;
                    res_g[128 + t * MAX_DYN + picked + pre] = g;
                }
                int got = __popc(m); if (got > K) got = K;
                picked += got;
                __syncwarp();
            }
            if (lane >= picked && lane < MAX_DYN) {
                res_p[128 + t * MAX_DYN + lane] = -1;
                res_g[128 + t * MAX_DYN + lane] = -1;
            }
            __syncwarp();
        }
    }
    __syncthreads();
    for (int i = tid; i < 1408; i += blockDim.x) {
        out[i]        = (float)res_p[i];
        out[1408 + i] = (float)res_g[i];
    }
}

// ------------------- launch (inputs resolved by element count) -------------------
extern "C" void kernel_launch(void* const* d_in, const int* in_sizes, int n_in,
                              void* d_out, int out_size) {
    const float* all_centers = 0;
    const float* all_sizes   = 0;
    const float* all_cls     = 0;
    const float* gt_centers  = 0;
    const float* gt_sizes    = 0;
    const void*  gt_labels   = 0;
    int seen196 = 0, seen384 = 0;
    for (int i = 0; i < n_in; i++) {
        long long s = in_sizes[i];
        if (s == (long long)N_PRED * N_CLS) {
            all_cls = (const float*)d_in[i];
        } else if (s == (long long)N_PRED * 3) {
            if (seen196++ == 0) all_centers = (const float*)d_in[i];
            else                all_sizes   = (const float*)d_in[i];
        } else if (s == (long long)N_GT * 3) {
            if (seen384++ == 0) gt_centers = (const float*)d_in[i];
            else                gt_sizes   = (const float*)d_in[i];
        } else if (s == (long long)N_GT) {
            gt_labels = d_in[i];
        }
    }

    cudaFuncSetAttribute(k_lsa, cudaFuncAttributeMaxDynamicSharedMemorySize, LSA_DYN_BYTES);

    k_labels<<<1, 128>>>(gt_labels);
    k_cost<<<N_PRED / 128, 512>>>(all_centers, all_sizes, all_cls, gt_centers, gt_sizes);
    k_select<<<2 * N_GT, 512>>>();
    k_lsa<<<1, 256, LSA_DYN_BYTES>>>();
    k_dyn<<<1, 256>>>((float*)d_out);
}

// round 9
// speedup vs baseline: 5.0666x; 1.1623x over previous
#include <cuda_runtime.h>
#include <math.h>
#include <stdint.h>

#define N_PRED 65536
#define N_GT   128
#define N_CLS  256
#define MAX_DYN 10
#define GEPS   1e-6f
#define IOU_THRES 0.25f
#define CAND_C 128      // per-row LSA candidates: exactly the 128 smallest
#define SEL_CAP 4096    // collection buffer cap (smem)
#define GC_NEED 1408    // per-gt dynamic candidate depth (10 + 128 + 10*127)
#define NBMW   (N_PRED/32)   // 2048 bitmap words
#define LSA_CAP 16512        // smem LSA capacity; union <= 128*128 = 16384 <= LSA_CAP
#define LSA_DYN_BYTES (LSA_CAP*12 + LSA_CAP/8)  // 200208

typedef unsigned long long ull;

// ------------------- scratch (device globals; no runtime allocation) -------------------
__device__ float  d_cost[N_GT][N_PRED];   // 32MB  cost_T[g][p]
__device__ float  d_giou[N_GT][N_PRED];   // 32MB  giou_T[g][p]
__device__ float  d_maxg[N_GT];
__device__ int    d_labels[N_GT];

__device__ int    d_ccand_idx[N_GT][CAND_C];  // sorted (cost,idx) asc; compact ids after remap
__device__ float  d_ccand_val[N_GT][CAND_C];
__device__ int    d_ccand_cnt[N_GT];

__device__ int    d_gcand_idx[N_GT][GC_NEED];
__device__ int    d_gcand_cnt[N_GT];

__device__ unsigned d_colbm[NBMW];
__device__ int    d_rev[N_PRED];          // compact id -> orig col
__device__ double d_v[N_PRED];            // column duals (compact-indexed)

// monotonic ascending key for float
__device__ __forceinline__ unsigned fkey(float f) {
    unsigned u = __float_as_uint(f);
    return (u & 0x80000000u) ? ~u : (u | 0x80000000u);
}

// block bitonic sort, ascending, n = power of two >= blockDim
__device__ __forceinline__ void bsort(ull* a, int n, int tid, int nth) {
    for (int k = 2; k <= n; k <<= 1) {
        for (int j = k >> 1; j > 0; j >>= 1) {
            for (int i = tid; i < n; i += nth) {
                int ixj = i ^ j;
                if (ixj > i) {
                    bool up = ((i & k) == 0);
                    ull x = a[i], y = a[ixj];
                    if ((x > y) == up) { a[i] = y; a[ixj] = x; }
                }
            }
            __syncthreads();
        }
    }
}

// ------------------- labels decode + bitmap zero -------------------
__global__ void k_labels(const void* lab) {
    __shared__ int is32;
    if (threadIdx.x == 0) {
        const ull* p = (const ull*)lab;
        int f = 0;
        for (int i = 0; i < 64; i++) { if (p[i] >> 32) { f = 1; break; } }
        is32 = f;
    }
    __syncthreads();
    int t = threadIdx.x;
    if (t < N_GT) {
        long long v;
        if (is32) v = (long long)((const int*)lab)[t];
        else      v = ((const long long*)lab)[t];
        int iv = (int)v;
        if (iv < 0) iv = 0;
        if (iv >= N_CLS) iv = N_CLS - 1;
        d_labels[t] = iv;
    }
    for (int i = t; i < NBMW; i += blockDim.x) d_colbm[i] = 0u;
}

// ------------------- cost + giou matrices (validated fp32; 4-way g-split) -------------
__global__ void k_cost(const float* __restrict__ pc, const float* __restrict__ ps,
                       const float* __restrict__ cls,
                       const float* __restrict__ gc, const float* __restrict__ gs) {
    __shared__ float glo0[N_GT], glo1[N_GT], glo2[N_GT];
    __shared__ float ghi0[N_GT], ghi1[N_GT], ghi2[N_GT];
    __shared__ float gvol[N_GT];
    __shared__ int   glab[N_GT];
    int tid = threadIdx.x;  // blockDim = 512
    if (tid < N_GT) {
        int t = tid;
        float c0 = gc[t*3+0], c1 = gc[t*3+1], c2 = gc[t*3+2];
        float s0 = gs[t*3+0], s1 = gs[t*3+1], s2 = gs[t*3+2];
        float h0s = __fmul_rn(s0, 0.5f), h1s = __fmul_rn(s1, 0.5f), h2s = __fmul_rn(s2, 0.5f);
        float l0 = __fsub_rn(c0, h0s), l1 = __fsub_rn(c1, h1s), l2 = __fsub_rn(c2, h2s);
        float h0 = __fadd_rn(c0, h0s), h1 = __fadd_rn(c1, h1s), h2 = __fadd_rn(c2, h2s);
        glo0[t]=l0; glo1[t]=l1; glo2[t]=l2; ghi0[t]=h0; ghi1[t]=h1; ghi2[t]=h2;
        gvol[t] = __fmul_rn(__fmul_rn(__fsub_rn(h0,l0), __fsub_rn(h1,l1)), __fsub_rn(h2,l2));
        glab[t] = d_labels[t];
    }
    __syncthreads();
    int p = blockIdx.x * 128 + (tid & 127);
    int gbase = (tid >> 7) * 32;          // 4 quarters of the g-loop
    float c0 = pc[p*3+0], c1 = pc[p*3+1], c2 = pc[p*3+2];
    float s0 = ps[p*3+0], s1 = ps[p*3+1], s2 = ps[p*3+2];
    float h0s = __fmul_rn(s0, 0.5f), h1s = __fmul_rn(s1, 0.5f), h2s = __fmul_rn(s2, 0.5f);
    float pl0 = __fsub_rn(c0, h0s), pl1 = __fsub_rn(c1, h1s), pl2 = __fsub_rn(c2, h2s);
    float ph0 = __fadd_rn(c0, h0s), ph1 = __fadd_rn(c1, h1s), ph2 = __fadd_rn(c2, h2s);
    float vol1 = __fmul_rn(__fmul_rn(__fsub_rn(ph0,pl0), __fsub_rn(ph1,pl1)), __fsub_rn(ph2,pl2));
    const float* clsrow = cls + (size_t)p * N_CLS;

    #pragma unroll 4
    for (int gi_ = 0; gi_ < 32; gi_++) {
        int g = gbase + gi_;
        float d0 = fmaxf(__fsub_rn(fminf(ph0, ghi0[g]), fmaxf(pl0, glo0[g])), 0.f);
        float d1 = fmaxf(__fsub_rn(fminf(ph1, ghi1[g]), fmaxf(pl1, glo1[g])), 0.f);
        float d2 = fmaxf(__fsub_rn(fminf(ph2, ghi2[g]), fmaxf(pl2, glo2[g])), 0.f);
        float ov = __fmul_rn(__fmul_rn(d0, d1), d2);
        float un = fmaxf(__fsub_rn(__fadd_rn(vol1, gvol[g]), ov), GEPS);
        float iou = __fdiv_rn(ov, un);
        float e0 = fmaxf(__fsub_rn(fmaxf(ph0, ghi0[g]), fminf(pl0, glo0[g])), 0.f);
        float e1 = fmaxf(__fsub_rn(fmaxf(ph1, ghi1[g]), fminf(pl1, glo1[g])), 0.f);
        float e2 = fmaxf(__fsub_rn(fmaxf(ph2, ghi2[g]), fminf(pl2, glo2[g])), 0.f);
        float enc = fmaxf(__fmul_rn(__fmul_rn(e0, e1), e2), GEPS);
        float gg = __fsub_rn(iou, __fdiv_rn(__fsub_rn(enc, un), enc));
        float cv = __ldg(clsrow + glab[g]);
        float sig = __fdiv_rn(1.0f, __fadd_rn(1.0f, expf(-cv)));
        d_giou[g][p] = gg;
        d_cost[g][p] = __fadd_rn(-sig, __fmul_rn(-2.0f, gg));
    }
}

// ------------------- selection: single-pass sample-threshold + sort -------------------
__global__ void k_select() {
    __shared__ ull buf[SEL_CAP];     // 32KB (aliased as hist in rare fallbacks)
    __shared__ ull samp[512];
    __shared__ float redf[512];
    __shared__ int s_cnt, s_c;

    int b = blockIdx.x, tid = threadIdx.x, nth = blockDim.x;  // nth = 512
    unsigned* hist = (unsigned*)buf;   // 2048-bin fallback histogram

    if (b < N_GT) {
        // ================= cost row =================
        int row = b;
        const float* crow = d_cost[row];
        if (tid < 512) {
            float v = crow[tid * 128];
            samp[tid] = ((ull)fkey(v) << 32) | (unsigned)(tid * 128);
        }
        __syncthreads();
        bsort(samp, 512, tid, nth);

        const int slist[5] = {4, 16, 64, 255, 511};
        int si = 0, cc = 0, truecnt = 0;
        while (true) {
            if (tid == 0) s_cnt = 0;
            __syncthreads();
            unsigned Tkey = (unsigned)(samp[slist[si]] >> 32);
            for (int j = tid; j < N_PRED; j += nth) {
                unsigned k = fkey(crow[j]);
                if (k <= Tkey) {
                    int slot = atomicAdd(&s_cnt, 1);
                    if (slot < SEL_CAP) buf[slot] = ((ull)k << 32) | (unsigned)j;
                }
            }
            __syncthreads();
            truecnt = s_cnt;
            cc = (truecnt < SEL_CAP) ? truecnt : SEL_CAP;
            if (truecnt >= CAND_C && truecnt <= SEL_CAP) break;
            if (truecnt > SEL_CAP) {
                for (int i = tid; i < 2048; i += nth) hist[i] = 0;
                __syncthreads();
                for (int j = tid; j < N_PRED; j += nth)
                    atomicAdd(&hist[fkey(crow[j]) >> 21], 1u);
                __syncthreads();
                if (tid == 0) {
                    unsigned need = CAND_C, cum = 0; int bb = 0;
                    for (; bb < 2047; bb++) { if (cum + hist[bb] >= need) break; cum += hist[bb]; }
                    s_c = bb; s_cnt = (int)(need - cum);
                }
                __syncthreads();
                unsigned pfx11 = (unsigned)s_c; int need1 = s_cnt;
                __syncthreads();
                for (int i = tid; i < 2048; i += nth) hist[i] = 0;
                __syncthreads();
                for (int j = tid; j < N_PRED; j += nth) {
                    unsigned k = fkey(crow[j]);
                    if ((k >> 21) == pfx11) atomicAdd(&hist[(k >> 10) & 2047u], 1u);
                }
                __syncthreads();
                if (tid == 0) {
                    unsigned need = (unsigned)need1, cum = 0; int bb = 0;
                    for (; bb < 2047; bb++) { if (cum + hist[bb] >= need) break; cum += hist[bb]; }
                    s_c = (int)((pfx11 << 11) | (unsigned)bb);
                    s_cnt = 0;
                }
                __syncthreads();
                unsigned pfx22 = (unsigned)s_c;
                __syncthreads();
                for (int j = tid; j < N_PRED; j += nth) {
                    unsigned k = fkey(crow[j]);
                    if ((k >> 10) <= pfx22) {
                        int slot = atomicAdd(&s_cnt, 1);
                        if (slot < SEL_CAP) buf[slot] = ((ull)k << 32) | (unsigned)j;
                    }
                }
                __syncthreads();
                truecnt = s_cnt;
                cc = (truecnt < SEL_CAP) ? truecnt : SEL_CAP;
                break;
            }
            si++;
            if (si >= 5) break;
            __syncthreads();
        }
        int n2 = 512; while (n2 < cc) n2 <<= 1;
        for (int i = tid + cc; i < n2; i += nth) buf[i] = 0xFFFFFFFFFFFFFFFFull;
        __syncthreads();
        bsort(buf, n2, tid, nth);
        int keep = (cc < CAND_C) ? cc : CAND_C;
        for (int i = tid; i < keep; i += nth) {
            ull e = buf[i];
            int j = (int)(e & 0xFFFFFFFFull);
            d_ccand_idx[row][i] = j;
            d_ccand_val[row][i] = crow[j];
            atomicOr(&d_colbm[j >> 5], 1u << (j & 31));
        }
        if (tid == 0) d_ccand_cnt[row] = keep;
    } else {
        // ================= giou row: fused max + collect =================
        int row = b - N_GT;
        const float* grow = d_giou[row];
        if (tid == 0) s_cnt = 0;
        __syncthreads();
        float lmax = -1e30f;
        for (int j = tid; j < N_PRED; j += nth) {
            float g = grow[j];
            lmax = fmaxf(lmax, g);
            if (g > IOU_THRES) {
                int slot = atomicAdd(&s_cnt, 1);
                if (slot < SEL_CAP) buf[slot] = ((ull)(~fkey(g)) << 32) | (unsigned)j;
            }
        }
        redf[tid] = lmax;
        __syncthreads();
        for (int off = nth >> 1; off > 0; off >>= 1) {
            if (tid < off) redf[tid] = fmaxf(redf[tid], redf[tid + off]);
            __syncthreads();
        }
        if (tid == 0) d_maxg[row] = redf[0];
        int tot = s_cnt;
        __syncthreads();
        if (tot > SEL_CAP) {
            for (int i = tid; i < 2048; i += nth) hist[i] = 0;
            __syncthreads();
            for (int j = tid; j < N_PRED; j += nth) {
                float g = grow[j];
                if (g > IOU_THRES) atomicAdd(&hist[(~fkey(g)) >> 21], 1u);
            }
            __syncthreads();
            if (tid == 0) {
                unsigned need = GC_NEED, cum = 0; int bb = 0;
                for (; bb < 2047; bb++) { if (cum + hist[bb] >= need) break; cum += hist[bb]; }
                s_c = bb; s_cnt = (int)(need - cum);
            }
            __syncthreads();
            unsigned pfx11 = (unsigned)s_c; int need1 = s_cnt;
            __syncthreads();
            for (int i = tid; i < 2048; i += nth) hist[i] = 0;
            __syncthreads();
            for (int j = tid; j < N_PRED; j += nth) {
                float g = grow[j];
                if (g > IOU_THRES) {
                    unsigned k = ~fkey(g);
                    if ((k >> 21) == pfx11) atomicAdd(&hist[(k >> 10) & 2047u], 1u);
                }
            }
            __syncthreads();
            if (tid == 0) {
                unsigned need = (unsigned)need1, cum = 0; int bb = 0;
                for (; bb < 2047; bb++) { if (cum + hist[bb] >= need) break; cum += hist[bb]; }
                s_c = (int)((pfx11 << 11) | (unsigned)bb);
                s_cnt = 0;
            }
            __syncthreads();
            unsigned pfx22 = (unsigned)s_c;
            __syncthreads();
            for (int j = tid; j < N_PRED; j += nth) {
                float g = grow[j];
                if (!(g > IOU_THRES)) continue;
                unsigned k = ~fkey(g);
                if ((k >> 10) <= pfx22) {
                    int slot = atomicAdd(&s_cnt, 1);
                    if (slot < SEL_CAP) buf[slot] = ((ull)k << 32) | (unsigned)j;
                }
            }
            __syncthreads();
            tot = s_cnt;
        }
        int cc = (tot < SEL_CAP) ? tot : SEL_CAP;
        int n2 = 512; while (n2 < cc) n2 <<= 1;
        for (int i = tid + cc; i < n2; i += nth) buf[i] = 0xFFFFFFFFFFFFFFFFull;
        __syncthreads();
        bsort(buf, n2, tid, nth);   // key asc == giou desc, idx asc
        int cnt = (cc < GC_NEED) ? cc : GC_NEED;
        for (int i = tid; i < cnt; i += nth)
            d_gcand_idx[row][i] = (int)(buf[i] & 0xFFFFFFFFull);
        if (tid == 0) d_gcand_cnt[row] = cnt;
    }
}

// ------------------- LSA (compact+remap+greedy+augment) + dynamic assign + output -----
__global__ void k_lsa(float* __restrict__ out) {
    extern __shared__ unsigned char dsm[];
    double*   shS  = (double*)dsm;                         // [LSA_CAP] shortest
    uint16_t* shT  = (uint16_t*)(dsm + (size_t)LSA_CAP*8); // [LSA_CAP] touched list
    uint8_t*  shP  = dsm + (size_t)LSA_CAP*10;             // [LSA_CAP] path (row)
    uint8_t*  shR  = dsm + (size_t)LSA_CAP*11;             // [LSA_CAP] row4col (255=free)
    unsigned* shSC = (unsigned*)(dsm + (size_t)LSA_CAP*12);// [LSA_CAP/32] SC bitmap
    int*      cbase = (int*)shT;                            // alias: dead before augment

    __shared__ double u[N_GT];
    __shared__ int SR[N_GT];
    __shared__ int c4r[N_GT];
    __shared__ int pend[N_GT];
    __shared__ int scnt[N_GT];
    __shared__ float s0val[N_GT];
    __shared__ int   s0idx[N_GT];
    __shared__ int   colro[N_GT];
    __shared__ double rv[8];
    __shared__ int ri[8];
    __shared__ int tsum[256];
    __shared__ int s_nSR, s_row, s_sink, s_nT, s_npend;
    __shared__ double s_minval;

    int tid = threadIdx.x, nth = blockDim.x;  // 256
    const double DINF = 1e300;

    // ---- compact scan of column bitmap ----
    int wbase = tid * 8;
    int cnts8[8]; int ssum = 0;
    #pragma unroll
    for (int w = 0; w < 8; w++) { cnts8[w] = __popc(d_colbm[wbase + w]); ssum += cnts8[w]; }
    tsum[tid] = ssum;
    __syncthreads();
    for (int off = 1; off < 256; off <<= 1) {
        int v_ = 0;
        if (tid >= off) v_ = tsum[tid - off];
        __syncthreads();
        tsum[tid] += v_;
        __syncthreads();
    }
    int excl = tsum[tid] - ssum;
    #pragma unroll
    for (int w = 0; w < 8; w++) { cbase[wbase + w] = excl; excl += cnts8[w]; }
    __syncthreads();
    int nK = tsum[255];
    if (nK > LSA_CAP) nK = LSA_CAP;   // impossible (union <= 16384), safety only

    // ---- remap candidates to compact ids + reverse map; zero duals ----
    for (int x = tid; x < N_GT * CAND_C; x += nth) {
        int row = x >> 7, s = x & 127;
        if (s < d_ccand_cnt[row]) {
            int j = d_ccand_idx[row][s];
            int w = j >> 5;
            int cid = cbase[w] + __popc(d_colbm[w] & ((1u << (j & 31)) - 1u));
            d_ccand_idx[row][s] = cid;
            d_rev[cid] = j;
        }
    }
    for (int i = tid; i < nK; i += nth) d_v[i] = 0.0;
    __syncthreads();   // cbase (shT alias) dead after this

    // ---- parallel prefetch of slot-0 data (kills serial global-latency chain) ----
    if (tid < N_GT) {
        scnt[tid]  = d_ccand_cnt[tid];
        s0val[tid] = d_ccand_val[tid][0];
        s0idx[tid] = d_ccand_idx[tid][0];
    }
    // ---- init smem LSA state ----
    for (int i = tid; i < nK; i += nth) shS[i] = DINF;
    for (int i = tid; i < nK; i += nth) shR[i] = 0xFF;
    for (int i = tid; i < (nK + 31) / 32; i += nth) shSC[i] = 0;
    if (tid < N_GT) c4r[tid] = -1;
    __syncthreads();

    // ---- greedy tight assignment (pure smem) ----
    if (tid == 0) {
        s_npend = 0;
        for (int i = 0; i < N_GT; i++) {
            if (scnt[i] > 0) {
                u[i] = (double)s0val[i];
                int j = s0idx[i];
                if (j >= 0 && j < nK && shR[j] == 0xFF) {
                    shR[j] = (uint8_t)i; c4r[i] = j;
                    continue;
                }
            } else u[i] = 0.0;
            pend[s_npend++] = i;
        }
    }
    __syncthreads();
    int npend = s_npend;

    // ---- shortest augmenting path per conflicted row ----
    for (int pi = 0; pi < npend; pi++) {
        int cur = pend[pi];
        if (tid == 0) { s_nSR = 0; s_row = cur; s_sink = -1; s_nT = 0; s_minval = 0.0; }
        __syncthreads();
        for (int step = 0; step < N_GT; step++) {
            int i = s_row;
            if (tid == 0) SR[s_nSR++] = i;
            double mv0 = s_minval, ui = u[i];
            int cnt = scnt[i];
            for (int s = tid; s < cnt; s += nth) {
                int jc = d_ccand_idx[i][s];
                if ((shSC[jc >> 5] >> (jc & 31)) & 1u) continue;
                double r = ((mv0 + (double)d_ccand_val[i][s]) - ui) - d_v[jc];
                double old = shS[jc];
                if (r < old) {
                    if (old == DINF) { int t2 = atomicAdd(&s_nT, 1); shT[t2] = (uint16_t)jc; }
                    shS[jc] = r; shP[jc] = (uint8_t)i;
                }
            }
            __syncthreads();
            double bv = DINF; int bj = 0x7fffffff;
            int nT = s_nT;
            for (int t2 = tid; t2 < nT; t2 += nth) {
                int jc = shT[t2];
                if ((shSC[jc >> 5] >> (jc & 31)) & 1u) continue;
                double sv = shS[jc];
                if (sv < bv || (sv == bv && jc < bj)) { bv = sv; bj = jc; }
            }
            // warp-level argmin, then 8 partials
            #pragma unroll
            for (int off = 16; off > 0; off >>= 1) {
                double ov = __shfl_down_sync(0xffffffffu, bv, off);
                int   oj = __shfl_down_sync(0xffffffffu, bj, off);
                if (ov < bv || (ov == bv && oj < bj)) { bv = ov; bj = oj; }
            }
            if ((tid & 31) == 0) { rv[tid >> 5] = bv; ri[tid >> 5] = bj; }
            __syncthreads();
            if (tid == 0) {
                double fbv = rv[0]; int fbj = ri[0];
                #pragma unroll
                for (int k = 1; k < 8; k++) {
                    if (rv[k] < fbv || (rv[k] == fbv && ri[k] < fbj)) { fbv = rv[k]; fbj = ri[k]; }
                }
                if (fbj >= 0 && fbj < nK) {
                    s_minval = fbv;
                    shSC[fbj >> 5] |= (1u << (fbj & 31));
                    int r4 = shR[fbj];
                    if (r4 == 0xFF) s_sink = fbj; else s_row = r4;
                } else s_sink = -2;
            }
            __syncthreads();
            if (s_sink != -1) break;
        }
        if (s_sink >= 0) {
            if (tid == 0) {
                u[cur] += s_minval;
                for (int k = 1; k < s_nSR; k++) {
                    int i2 = SR[k];
                    u[i2] += s_minval - shS[c4r[i2]];
                }
            }
            int nT = s_nT; double mv = s_minval;
            for (int t2 = tid; t2 < nT; t2 += nth) {
                int jc = shT[t2];
                if ((shSC[jc >> 5] >> (jc & 31)) & 1u) d_v[jc] -= mv - shS[jc];
            }
            __syncthreads();
            if (tid == 0) {
                int j = s_sink;
                for (int it = 0; it <= N_GT && j >= 0; it++) {
                    int i2 = shP[j];
                    shR[j] = (uint8_t)i2;
                    int tmp = c4r[i2];
                    c4r[i2] = j;
                    j = tmp;
                    if (i2 == cur) break;
                }
            }
        }
        __syncthreads();
        int nT = s_nT;
        for (int t2 = tid; t2 < nT; t2 += nth) shS[shT[t2]] = DINF;
        for (int i = tid; i < (nK + 31) / 32; i += nth) shSC[i] = 0;
        __syncthreads();
    }
    if (tid < N_GT) colro[tid] = (c4r[tid] >= 0) ? d_rev[c4r[tid]] : -1;
    __syncthreads();

    // ================= dynamic assignment phase (reuses dead dsm region) =================
    unsigned* used = (unsigned*)dsm;                    // 8KB
    int* res_p = (int*)(dsm + 8192);                    // 5632B
    int* res_g = (int*)(dsm + 8192 + 5632);             // 5632B
    int* pref  = (int*)(dsm + 19456);                   // 16KB: pref[g*32+s]
    int* gcnts = (int*)(dsm + 35840);                   // 512B
    int* ordv  = (int*)(dsm + 36352);                   // 512B
    float* mg  = (float*)(dsm + 36864);                 // 512B

    for (int i = tid; i < NBMW; i += nth) used[i] = 0;
    if (tid < N_GT) { gcnts[tid] = d_gcand_cnt[tid]; mg[tid] = d_maxg[tid]; }
    __syncthreads();
    // stable ascending argsort of maxg
    if (tid < N_GT) {
        float mv = mg[tid]; int r = 0;
        for (int j = 0; j < N_GT; j++) {
            float o = mg[j];
            if (o < mv || (o == mv && j < tid)) r++;
        }
        ordv[r] = tid;
    }
    for (int i = tid; i < N_GT * 32; i += nth) {
        int g = i >> 5, s = i & 31;
        pref[i] = (s < gcnts[g]) ? d_gcand_idx[g][s] : -1;
    }
    if (tid < N_GT) {
        int p = colro[tid];
        if (p >= 0 && p < N_PRED) atomicOr(&used[p >> 5], 1u << (p & 31));
        res_p[tid] = p;
        res_g[tid] = tid;
    }
    __syncthreads();
    if (tid < 32) {
        int lane = tid;
        for (int t = 0; t < N_GT; t++) {
            int g = ordv[t];
            int cnt = gcnts[g];
            int picked = 0;
            for (int base = 0; base < cnt && picked < MAX_DYN; base += 32) {
                int idx = -1;
                if (base + lane < cnt)
                    idx = (base == 0) ? pref[g * 32 + lane] : d_gcand_idx[g][base + lane];
                bool elig = (idx >= 0) && (idx < N_PRED) && !((used[idx >> 5] >> (idx & 31)) & 1u);
                unsigned m = __ballot_sync(0xffffffffu, elig);
                int K = MAX_DYN - picked;
                int pre = __popc(m & ((1u << lane) - 1u));
                if (elig && pre < K) {
                    atomicOr(&used[idx >> 5], 1u << (idx & 31));
                    res_p[128 + t * MAX_DYN + picked + pre] = idx;
                    res_g[128 + t * MAX_DYN + picked + pre] = g;
                }
                int got = __popc(m); if (got > K) got = K;
                picked += got;
                __syncwarp();
            }
            if (lane >= picked && lane < MAX_DYN) {
                res_p[128 + t * MAX_DYN + lane] = -1;
                res_g[128 + t * MAX_DYN + lane] = -1;
            }
            __syncwarp();
        }
    }
    __syncthreads();
    for (int i = tid; i < 1408; i += nth) {
        out[i]        = (float)res_p[i];
        out[1408 + i] = (float)res_g[i];
    }
}

// ------------------- launch (inputs resolved by element count) -------------------
extern "C" void kernel_launch(void* const* d_in, const int* in_sizes, int n_in,
                              void* d_out, int out_size) {
    const float* all_centers = 0;
    const float* all_sizes   = 0;
    const float* all_cls     = 0;
    const float* gt_centers  = 0;
    const float* gt_sizes    = 0;
    const void*  gt_labels   = 0;
    int seen196 = 0, seen384 = 0;
    for (int i = 0; i < n_in; i++) {
        long long s = in_sizes[i];
        if (s == (long long)N_PRED * N_CLS) {
            all_cls = (const float*)d_in[i];
        } else if (s == (long long)N_PRED * 3) {
            if (seen196++ == 0) all_centers = (const float*)d_in[i];
            else                all_sizes   = (const float*)d_in[i];
        } else if (s == (long long)N_GT * 3) {
            if (seen384++ == 0) gt_centers = (const float*)d_in[i];
            else                gt_sizes   = (const float*)d_in[i];
        } else if (s == (long long)N_GT) {
            gt_labels = d_in[i];
        }
    }

    cudaFuncSetAttribute(k_lsa, cudaFuncAttributeMaxDynamicSharedMemorySize, LSA_DYN_BYTES);

    k_labels<<<1, 128>>>(gt_labels);
    k_cost<<<N_PRED / 128, 512>>>(all_centers, all_sizes, all_cls, gt_centers, gt_sizes);
    k_select<<<2 * N_GT, 512>>>();
    k_lsa<<<1, 256, LSA_DYN_BYTES>>>((float*)d_out);
}